// round 1
// baseline (speedup 1.0000x reference)
#include <cuda_runtime.h>
#include <math.h>

// ---------------- problem constants ----------------
#define L_SEQ 16384
#define D_MOD 512
#define NH 8
#define DH 64
#define FF 2048
#define BATCH 2
#define EPS_F 1e-6f

// ---------------- scratch (static device globals; no allocation) ----------------
__device__ float g_h1[L_SEQ * D_MOD];          // ln1(x[0])
__device__ float g_q[L_SEQ * D_MOD];
__device__ float g_k[L_SEQ * D_MOD];
__device__ float g_v[L_SEQ * D_MOD];
__device__ float g_o[L_SEQ * D_MOD];
__device__ float g_sa[L_SEQ * D_MOD];
__device__ float g_x2[BATCH * L_SEQ * D_MOD];  // x + sa (residual, needed at end)
__device__ float g_ln2[BATCH * L_SEQ * D_MOD];
__device__ float g_t[BATCH * L_SEQ * FF];      // gelu(ln2 @ W1 + b1)

__device__ float g_ksum[D_MOD], g_qsum[D_MOD];
__device__ float g_kwsum[D_MOD], g_qwsum[D_MOD];
__device__ float g_sink_in[NH * L_SEQ];
__device__ float g_src_out[NH * L_SEQ];
__device__ float g_alloc[NH * L_SEQ];
__device__ float g_cs[NH * L_SEQ];
__device__ float g_hmax[NH], g_hsum[NH];
__device__ float g_kv[NH * DH * DH];

// ---------------- zero accumulators (deterministic per launch) ----------------
__global__ void zero_acc_kernel() {
    int t = blockIdx.x * blockDim.x + threadIdx.x;   // 128 blocks * 256 = 32768
    if (t < D_MOD) {
        g_ksum[t] = 0.f; g_qsum[t] = 0.f;
        g_kwsum[t] = 0.f; g_qwsum[t] = 0.f;
    }
    if (t < NH * DH * DH) g_kv[t] = 0.f;
}

// ---------------- layernorm on x[0] -> g_h1 ----------------
__global__ void ln1_kernel(const float* __restrict__ x,
                           const float* __restrict__ g,
                           const float* __restrict__ be) {
    __shared__ float sh1[4], sh2[4];
    int row = blockIdx.x;
    int t = threadIdx.x;  // 128
    const float* xr = x + (size_t)row * D_MOD;
    float v0 = xr[t], v1 = xr[t + 128], v2 = xr[t + 256], v3 = xr[t + 384];
    float s = v0 + v1 + v2 + v3;
    float s2 = v0 * v0 + v1 * v1 + v2 * v2 + v3 * v3;
    #pragma unroll
    for (int o = 16; o > 0; o >>= 1) {
        s += __shfl_down_sync(0xffffffffu, s, o);
        s2 += __shfl_down_sync(0xffffffffu, s2, o);
    }
    if ((t & 31) == 0) { sh1[t >> 5] = s; sh2[t >> 5] = s2; }
    __syncthreads();
    s = sh1[0] + sh1[1] + sh1[2] + sh1[3];
    s2 = sh2[0] + sh2[1] + sh2[2] + sh2[3];
    float m = s * (1.f / D_MOD);
    float var = s2 * (1.f / D_MOD) - m * m;
    float rstd = rsqrtf(var + 1e-5f);
    float* op = g_h1 + (size_t)row * D_MOD;
    op[t]       = (v0 - m) * rstd * g[t]       + be[t];
    op[t + 128] = (v1 - m) * rstd * g[t + 128] + be[t + 128];
    op[t + 256] = (v2 - m) * rstd * g[t + 256] + be[t + 256];
    op[t + 384] = (v3 - m) * rstd * g[t + 384] + be[t + 384];
}

// ---------------- x2 = x + sa(broadcast), ln2 = layernorm(x2) ----------------
__global__ void addln2_kernel(const float* __restrict__ x,
                              const float* __restrict__ g,
                              const float* __restrict__ be) {
    __shared__ float sh1[4], sh2[4];
    int row = blockIdx.x;               // 0..BATCH*L-1
    int l = row & (L_SEQ - 1);
    int t = threadIdx.x;  // 128
    const float* xr = x + (size_t)row * D_MOD;
    const float* sr = g_sa + (size_t)l * D_MOD;
    float v0 = xr[t] + sr[t];
    float v1 = xr[t + 128] + sr[t + 128];
    float v2 = xr[t + 256] + sr[t + 256];
    float v3 = xr[t + 384] + sr[t + 384];
    float* x2p = g_x2 + (size_t)row * D_MOD;
    x2p[t] = v0; x2p[t + 128] = v1; x2p[t + 256] = v2; x2p[t + 384] = v3;
    float s = v0 + v1 + v2 + v3;
    float s2 = v0 * v0 + v1 * v1 + v2 * v2 + v3 * v3;
    #pragma unroll
    for (int o = 16; o > 0; o >>= 1) {
        s += __shfl_down_sync(0xffffffffu, s, o);
        s2 += __shfl_down_sync(0xffffffffu, s2, o);
    }
    if ((t & 31) == 0) { sh1[t >> 5] = s; sh2[t >> 5] = s2; }
    __syncthreads();
    s = sh1[0] + sh1[1] + sh1[2] + sh1[3];
    s2 = sh2[0] + sh2[1] + sh2[2] + sh2[3];
    float m = s * (1.f / D_MOD);
    float var = s2 * (1.f / D_MOD) - m * m;
    float rstd = rsqrtf(var + 1e-5f);
    float* op = g_ln2 + (size_t)row * D_MOD;
    op[t]       = (v0 - m) * rstd * g[t]       + be[t];
    op[t + 128] = (v1 - m) * rstd * g[t + 128] + be[t + 128];
    op[t + 256] = (v2 - m) * rstd * g[t + 256] + be[t + 256];
    op[t + 384] = (v3 - m) * rstd * g[t + 384] + be[t + 384];
}

// ---------------- column sums of q, k ----------------
__global__ void colsum_qk_kernel() {
    int c = threadIdx.x;                 // 512 threads
    int r0 = blockIdx.x * 256;           // 64 blocks
    float sq = 0.f, sk = 0.f;
    for (int r = r0; r < r0 + 256; r++) {
        sq += g_q[(size_t)r * D_MOD + c];
        sk += g_k[(size_t)r * D_MOD + c];
    }
    atomicAdd(&g_qsum[c], sq);
    atomicAdd(&g_ksum[c], sk);
}

// ---------------- weighted column sums ----------------
__global__ void colsum_w_kernel() {
    int c = threadIdx.x;                 // 512 threads
    int h = c >> 6;
    int r0 = blockIdx.x * 256;           // 64 blocks
    float sq = 0.f, sk = 0.f;
    for (int r = r0; r < r0 + 256; r++) {
        float si = g_sink_in[h * L_SEQ + r];
        float so = g_src_out[h * L_SEQ + r];
        sq += g_q[(size_t)r * D_MOD + c] * si;
        sk += g_k[(size_t)r * D_MOD + c] * so;
    }
    atomicAdd(&g_qwsum[c], sq);
    atomicAdd(&g_kwsum[c], sk);
}

// ---------------- stage1: sink_incoming / source_outgoing ----------------
__global__ void stage1_kernel() {
    int w = (blockIdx.x * blockDim.x + threadIdx.x) >> 5;  // warp per (h,l)
    int lane = threadIdx.x & 31;
    int h = w >> 14;
    int l = w & (L_SEQ - 1);
    const float* qr = g_q + (size_t)l * D_MOD + h * DH;
    const float* kr = g_k + (size_t)l * D_MOD + h * DH;
    const float* ks = g_ksum + h * DH;
    const float* qs = g_qsum + h * DH;
    float a = (qr[lane] + EPS_F) * (ks[lane] + EPS_F)
            + (qr[lane + 32] + EPS_F) * (ks[lane + 32] + EPS_F);
    float b = (kr[lane] + EPS_F) * (qs[lane] + EPS_F)
            + (kr[lane + 32] + EPS_F) * (qs[lane + 32] + EPS_F);
    #pragma unroll
    for (int o = 16; o > 0; o >>= 1) {
        a += __shfl_down_sync(0xffffffffu, a, o);
        b += __shfl_down_sync(0xffffffffu, b, o);
    }
    if (lane == 0) {
        g_sink_in[h * L_SEQ + l] = 1.f / a;
        g_src_out[h * L_SEQ + l] = 1.f / b;
    }
}

// ---------------- stage2: sink_allocation / conserved_source ----------------
__global__ void stage2_kernel() {
    int w = (blockIdx.x * blockDim.x + threadIdx.x) >> 5;
    int lane = threadIdx.x & 31;
    int h = w >> 14;
    int l = w & (L_SEQ - 1);
    const float* qr = g_q + (size_t)l * D_MOD + h * DH;
    const float* kr = g_k + (size_t)l * D_MOD + h * DH;
    const float* kw = g_kwsum + h * DH;
    const float* qw = g_qwsum + h * DH;
    float a = (qr[lane] + EPS_F) * (kw[lane] + EPS_F)
            + (qr[lane + 32] + EPS_F) * (kw[lane + 32] + EPS_F);
    float b = (kr[lane] + EPS_F) * (qw[lane] + EPS_F)
            + (kr[lane + 32] + EPS_F) * (qw[lane + 32] + EPS_F);
    #pragma unroll
    for (int o = 16; o > 0; o >>= 1) {
        a += __shfl_down_sync(0xffffffffu, a, o);
        b += __shfl_down_sync(0xffffffffu, b, o);
    }
    if (lane == 0) {
        g_alloc[h * L_SEQ + l] = 1.f / (1.f + expf(-a));       // L/S == 1
        g_cs[h * L_SEQ + l] = fminf(fmaxf(b, -1.f), 1.f);
    }
}

// ---------------- per-head softmax stats over conserved_source ----------------
__global__ void softmax_head_kernel() {
    __shared__ float sh[32];
    int h = blockIdx.x;
    int t = threadIdx.x;  // 1024
    const float* cs = g_cs + h * L_SEQ;
    float mx = -1e30f;
    for (int i = t; i < L_SEQ; i += 1024) mx = fmaxf(mx, cs[i]);
    #pragma unroll
    for (int o = 16; o > 0; o >>= 1) mx = fmaxf(mx, __shfl_xor_sync(0xffffffffu, mx, o));
    if ((t & 31) == 0) sh[t >> 5] = mx;
    __syncthreads();
    float bm = sh[0];
    #pragma unroll
    for (int i = 1; i < 32; i++) bm = fmaxf(bm, sh[i]);
    __syncthreads();
    float se = 0.f;
    for (int i = t; i < L_SEQ; i += 1024) se += expf(cs[i] - bm);
    #pragma unroll
    for (int o = 16; o > 0; o >>= 1) se += __shfl_xor_sync(0xffffffffu, se, o);
    if ((t & 31) == 0) sh[t >> 5] = se;
    __syncthreads();
    if (t == 0) {
        float s = 0.f;
        #pragma unroll
        for (int i = 0; i < 32; i++) s += sh[i];
        g_hmax[h] = bm;
        g_hsum[h] = s;
    }
}

// ---------------- kv[h] = sum_l k[h,l,:]^T (v[h,l,:]*comp) ----------------
__global__ void kv_kernel() {
    __shared__ float sk[8][64];
    __shared__ float sv[8][64];
    int h = blockIdx.y;
    int chunk = blockIdx.x;   // 32 chunks of 512 rows
    int t = threadIdx.x;      // 256
    int drow = t >> 2;        // 0..63
    int mbase = (t & 3) << 4; // 0,16,32,48
    float hmax = g_hmax[h];
    float hscale = (float)L_SEQ / g_hsum[h];
    int l0 = chunk * 512;
    float acc[16];
    #pragma unroll
    for (int j = 0; j < 16; j++) acc[j] = 0.f;
    for (int it = 0; it < 64; it++) {
        int lb = l0 + it * 8;
        #pragma unroll
        for (int j = 0; j < 4; j++) {
            int e = t + j * 256;  // 0..1023
            if (e < 512) {
                int r = e >> 6, dd = e & 63;
                sk[r][dd] = g_k[(size_t)(lb + r) * D_MOD + h * DH + dd];
            } else {
                int e2 = e - 512;
                int r = e2 >> 6, dd = e2 & 63;
                int l = lb + r;
                float comp = expf(g_cs[h * L_SEQ + l] - hmax) * hscale;
                sv[r][dd] = g_v[(size_t)l * D_MOD + h * DH + dd] * comp;
            }
        }
        __syncthreads();
        #pragma unroll
        for (int r = 0; r < 8; r++) {
            float kd = sk[r][drow];
            #pragma unroll
            for (int j = 0; j < 16; j++) acc[j] += kd * sv[r][mbase + j];
        }
        __syncthreads();
    }
    float* kvp = g_kv + h * DH * DH + drow * DH + mbase;
    #pragma unroll
    for (int j = 0; j < 16; j++) atomicAdd(&kvp[j], acc[j]);
}

// ---------------- o = (q*sink_in) @ kv * alloc ----------------
__global__ void o_kernel() {
    __shared__ float kvs[DH * DH];
    __shared__ float qs[32][64];
    int h = blockIdx.y;
    int chunk = blockIdx.x;  // 512 chunks of 32 rows
    int t = threadIdx.x;     // 256
    for (int e = t; e < DH * DH; e += 256) kvs[e] = g_kv[h * DH * DH + e];
    for (int e = t; e < 32 * 64; e += 256) {
        int r = e >> 6, dd = e & 63;
        int l = chunk * 32 + r;
        qs[r][dd] = g_q[(size_t)l * D_MOD + h * DH + dd] * g_sink_in[h * L_SEQ + l];
    }
    __syncthreads();
    int r = t >> 3;
    int cg = (t & 7) * 8;
    float acc[8];
    #pragma unroll
    for (int j = 0; j < 8; j++) acc[j] = 0.f;
    #pragma unroll
    for (int dd = 0; dd < 64; dd++) {
        float qv = qs[r][dd];
        #pragma unroll
        for (int j = 0; j < 8; j++) acc[j] += qv * kvs[dd * 64 + cg + j];
    }
    int l = chunk * 32 + r;
    float al = g_alloc[h * L_SEQ + l];
    float* op = g_o + (size_t)l * D_MOD + h * DH + cg;
    #pragma unroll
    for (int j = 0; j < 8; j++) op[j] = acc[j] * al;
}

// ---------------- SGEMM: C = epilogue(A @ B + bias [, res]) ----------------
// A: [M,K] row-major, B: [K,N] row-major.
// MODE 0: +bias | 1: sigmoid | 2: gelu(erf) | 3: +bias+res
#define BM 128
#define BN 128
#define BK 16
template <int MODE>
__global__ __launch_bounds__(256) void sgemm_kernel(
    const float* __restrict__ A, const float* __restrict__ B,
    const float* __restrict__ bias, const float* __restrict__ res,
    float* __restrict__ C, int M, int N, int K) {
    __shared__ __align__(16) float As[BK][BM];
    __shared__ __align__(16) float Bs[BK][BN];
    int tid = threadIdx.x;
    int row0 = blockIdx.y * BM;
    int col0 = blockIdx.x * BN;
    int a_r = tid >> 2;
    int a_c = (tid & 3) << 2;
    int b_r = tid >> 5;
    int b_c = (tid & 31) << 2;
    int ty = tid >> 4, tx = tid & 15;
    float acc[8][8];
    #pragma unroll
    for (int i = 0; i < 8; i++)
        #pragma unroll
        for (int j = 0; j < 8; j++) acc[i][j] = 0.f;

    for (int k0 = 0; k0 < K; k0 += BK) {
        float4 a0 = *(const float4*)(A + (size_t)(row0 + a_r) * K + k0 + a_c);
        float4 a1 = *(const float4*)(A + (size_t)(row0 + a_r + 64) * K + k0 + a_c);
        As[a_c + 0][a_r] = a0.x; As[a_c + 1][a_r] = a0.y;
        As[a_c + 2][a_r] = a0.z; As[a_c + 3][a_r] = a0.w;
        As[a_c + 0][a_r + 64] = a1.x; As[a_c + 1][a_r + 64] = a1.y;
        As[a_c + 2][a_r + 64] = a1.z; As[a_c + 3][a_r + 64] = a1.w;
        float4 b0 = *(const float4*)(B + (size_t)(k0 + b_r) * N + col0 + b_c);
        float4 b1 = *(const float4*)(B + (size_t)(k0 + b_r + 8) * N + col0 + b_c);
        *(float4*)(&Bs[b_r][b_c]) = b0;
        *(float4*)(&Bs[b_r + 8][b_c]) = b1;
        __syncthreads();
        #pragma unroll
        for (int kk = 0; kk < BK; kk++) {
            float af[8], bf[8];
            *(float4*)(&af[0]) = *(const float4*)(&As[kk][ty * 8]);
            *(float4*)(&af[4]) = *(const float4*)(&As[kk][ty * 8 + 4]);
            *(float4*)(&bf[0]) = *(const float4*)(&Bs[kk][tx * 8]);
            *(float4*)(&bf[4]) = *(const float4*)(&Bs[kk][tx * 8 + 4]);
            #pragma unroll
            for (int i = 0; i < 8; i++)
                #pragma unroll
                for (int j = 0; j < 8; j++) acc[i][j] += af[i] * bf[j];
        }
        __syncthreads();
    }

    const float* bp = bias + col0 + tx * 8;
    #pragma unroll
    for (int i = 0; i < 8; i++) {
        size_t r = (size_t)(row0 + ty * 8 + i);
        float* cp = C + r * N + col0 + tx * 8;
        const float* rp = (MODE == 3) ? (res + r * N + col0 + tx * 8) : nullptr;
        #pragma unroll
        for (int j = 0; j < 8; j++) {
            float vv = acc[i][j] + bp[j];
            if (MODE == 1) {
                vv = 1.f / (1.f + expf(-vv));
            } else if (MODE == 2) {
                vv = 0.5f * vv * (1.f + erff(vv * 0.70710678118654752f));
            } else if (MODE == 3) {
                vv += rp[j];
            }
            cp[j] = vv;
        }
    }
}

// ---------------- launcher ----------------
extern "C" void kernel_launch(void* const* d_in, const int* in_sizes, int n_in,
                              void* d_out, int out_size) {
    (void)in_sizes; (void)n_in; (void)out_size;
    const float* x   = (const float*)d_in[0];
    const float* Wq  = (const float*)d_in[1];
    const float* bq  = (const float*)d_in[2];
    const float* Wk  = (const float*)d_in[3];
    const float* bk  = (const float*)d_in[4];
    const float* Wv  = (const float*)d_in[5];
    const float* bv  = (const float*)d_in[6];
    const float* Wo  = (const float*)d_in[7];
    const float* bo  = (const float*)d_in[8];
    const float* W1  = (const float*)d_in[9];
    const float* b1  = (const float*)d_in[10];
    const float* W2  = (const float*)d_in[11];
    const float* b2  = (const float*)d_in[12];
    const float* g1  = (const float*)d_in[13];
    const float* be1 = (const float*)d_in[14];
    const float* g2  = (const float*)d_in[15];
    const float* be2 = (const float*)d_in[16];
    float* out = (float*)d_out;

    float *p_h1, *p_q, *p_k, *p_v, *p_o, *p_sa, *p_x2, *p_ln2, *p_t;
    cudaGetSymbolAddress((void**)&p_h1, g_h1);
    cudaGetSymbolAddress((void**)&p_q, g_q);
    cudaGetSymbolAddress((void**)&p_k, g_k);
    cudaGetSymbolAddress((void**)&p_v, g_v);
    cudaGetSymbolAddress((void**)&p_o, g_o);
    cudaGetSymbolAddress((void**)&p_sa, g_sa);
    cudaGetSymbolAddress((void**)&p_x2, g_x2);
    cudaGetSymbolAddress((void**)&p_ln2, g_ln2);
    cudaGetSymbolAddress((void**)&p_t, g_t);

    zero_acc_kernel<<<128, 256>>>();
    ln1_kernel<<<L_SEQ, 128>>>(x, g1, be1);

    dim3 gqkv(D_MOD / BN, L_SEQ / BM);            // (4, 128)
    sgemm_kernel<1><<<gqkv, 256>>>(p_h1, Wq, bq, nullptr, p_q, L_SEQ, D_MOD, D_MOD);
    sgemm_kernel<1><<<gqkv, 256>>>(p_h1, Wk, bk, nullptr, p_k, L_SEQ, D_MOD, D_MOD);
    sgemm_kernel<0><<<gqkv, 256>>>(p_h1, Wv, bv, nullptr, p_v, L_SEQ, D_MOD, D_MOD);

    colsum_qk_kernel<<<64, 512>>>();
    stage1_kernel<<<(NH * L_SEQ) / 8, 256>>>();
    colsum_w_kernel<<<64, 512>>>();
    stage2_kernel<<<(NH * L_SEQ) / 8, 256>>>();
    softmax_head_kernel<<<NH, 1024>>>();
    kv_kernel<<<dim3(32, NH), 256>>>();
    o_kernel<<<dim3(L_SEQ / 32, NH), 256>>>();

    sgemm_kernel<0><<<gqkv, 256>>>(p_o, Wo, bo, nullptr, p_sa, L_SEQ, D_MOD, D_MOD);

    addln2_kernel<<<BATCH * L_SEQ, 128>>>(x, g2, be2);

    dim3 gf1(FF / BN, (BATCH * L_SEQ) / BM);       // (16, 256)
    sgemm_kernel<2><<<gf1, 256>>>(p_ln2, W1, b1, nullptr, p_t, BATCH * L_SEQ, FF, D_MOD);

    dim3 gf2(D_MOD / BN, (BATCH * L_SEQ) / BM);    // (4, 256)
    sgemm_kernel<3><<<gf2, 256>>>(p_t, W2, b2, p_x2, out, BATCH * L_SEQ, D_MOD, FF);
}

// round 3
// speedup vs baseline: 1.7022x; 1.7022x over previous
#include <cuda_runtime.h>
#include <cuda_bf16.h>
#include <math.h>
#include <stdint.h>

// ---------------- problem constants ----------------
#define L_SEQ 16384
#define D_MOD 512
#define NH 8
#define DH 64
#define FF 2048
#define BATCH 2
#define EPS_F 1e-6f

// GEMM tiling
#define TILE 128
#define KC 32
#define STAGES 4
#define AROW_B 80                       // padded smem row bytes (32 bf16 data + 16B pad)
#define HALF_STAGE (128 * AROW_B)       // 10240
#define STAGE_B (2 * HALF_STAGE)        // 20480 (A + B)
#define SMEM_SZ (STAGES * STAGE_B)      // 81920

// ---------------- scratch (static device globals; no allocation) ----------------
__device__ __align__(128) __nv_bfloat16 g_h1s[L_SEQ * 2 * D_MOD];           // ln1(x[0]) split [hi|lo]
__device__ __align__(128) __nv_bfloat16 g_os [L_SEQ * 2 * D_MOD];           // attn out split
__device__ __align__(128) __nv_bfloat16 g_ln2s[BATCH * L_SEQ * 2 * D_MOD];  // ln2 split
__device__ __align__(128) __nv_bfloat16 g_ts [(size_t)BATCH * L_SEQ * 2 * FF]; // gelu(ffn1) split
__device__ __align__(128) __nv_bfloat16 g_Wqs[D_MOD * 2 * D_MOD];
__device__ __align__(128) __nv_bfloat16 g_Wks[D_MOD * 2 * D_MOD];
__device__ __align__(128) __nv_bfloat16 g_Wvs[D_MOD * 2 * D_MOD];
__device__ __align__(128) __nv_bfloat16 g_Wos[D_MOD * 2 * D_MOD];
__device__ __align__(128) __nv_bfloat16 g_W1s[FF * 2 * D_MOD];
__device__ __align__(128) __nv_bfloat16 g_W2s[D_MOD * 2 * FF];

__device__ __align__(16) float g_q[L_SEQ * D_MOD];
__device__ __align__(16) float g_k[L_SEQ * D_MOD];
__device__ __align__(16) float g_v[L_SEQ * D_MOD];
__device__ __align__(16) float g_sa[L_SEQ * D_MOD];
__device__ __align__(16) float g_x2[BATCH * L_SEQ * D_MOD];

__device__ float g_ksum[D_MOD], g_qsum[D_MOD];
__device__ float g_kwsum[D_MOD], g_qwsum[D_MOD];
__device__ float g_sink_in[NH * L_SEQ];
__device__ float g_src_out[NH * L_SEQ];
__device__ float g_alloc[NH * L_SEQ];
__device__ float g_cs[NH * L_SEQ];
__device__ float g_hmax[NH], g_hsum[NH];
__device__ float g_kv[NH * DH * DH];

// ---------------- PTX helpers (all baseline sm_80+/sm_90 features) ----------------
__device__ __forceinline__ uint32_t sm_u32(const void* p) {
    uint32_t a;
    asm("{ .reg .u64 t; cvta.to.shared.u64 t, %1; cvt.u32.u64 %0, t; }" : "=r"(a) : "l"(p));
    return a;
}
__device__ __forceinline__ void cp16(uint32_t s, const void* g) {
    asm volatile("cp.async.cg.shared.global [%0], [%1], 16;" :: "r"(s), "l"(g));
}
__device__ __forceinline__ void cp_commit() {
    asm volatile("cp.async.commit_group;" ::: "memory");
}
__device__ __forceinline__ void ldsm4(uint32_t* r, uint32_t addr) {
    asm volatile("ldmatrix.sync.aligned.m8n8.x4.shared.b16 {%0,%1,%2,%3}, [%4];"
                 : "=r"(r[0]), "=r"(r[1]), "=r"(r[2]), "=r"(r[3]) : "r"(addr));
}
__device__ __forceinline__ void mma16816(float* d, const uint32_t* a, const uint32_t* b) {
    asm volatile(
        "mma.sync.aligned.m16n8k16.row.col.f32.bf16.bf16.f32 "
        "{%0,%1,%2,%3}, {%4,%5,%6,%7}, {%8,%9}, {%0,%1,%2,%3};"
        : "+f"(d[0]), "+f"(d[1]), "+f"(d[2]), "+f"(d[3])
        : "r"(a[0]), "r"(a[1]), "r"(a[2]), "r"(a[3]), "r"(b[0]), "r"(b[1]));
}

__device__ __forceinline__ void wsplit2(__nv_bfloat16* hi, __nv_bfloat16* lo, float v) {
    __nv_bfloat16 h = __float2bfloat16(v);
    *hi = h;
    *lo = __float2bfloat16(v - __bfloat162float(h));
}

// ---------------- zero accumulators ----------------
__global__ void zero_acc_kernel() {
    int t = blockIdx.x * blockDim.x + threadIdx.x;
    if (t < D_MOD) { g_ksum[t] = 0.f; g_qsum[t] = 0.f; g_kwsum[t] = 0.f; g_qwsum[t] = 0.f; }
    if (t < NH * DH * DH) g_kv[t] = 0.f;
}

// ---------------- weight split-transpose: W[K,N] -> Wt[N, 2K] (hi|lo) ----------------
__global__ void wsplit_kernel(const float* __restrict__ W, __nv_bfloat16* __restrict__ Wt,
                              int K, int N) {
    __shared__ float tile[32][33];
    int k0 = blockIdx.y * 32, n0 = blockIdx.x * 32;
    int tx = threadIdx.x, ty = threadIdx.y;  // 32 x 8
    for (int i = ty; i < 32; i += 8) tile[i][tx] = W[(size_t)(k0 + i) * N + n0 + tx];
    __syncthreads();
    for (int i = ty; i < 32; i += 8) {
        float v = tile[tx][i];  // W[k0+tx][n0+i]
        size_t ro = (size_t)(n0 + i) * (2 * K) + k0 + tx;
        __nv_bfloat16 h = __float2bfloat16(v);
        Wt[ro] = h;
        Wt[ro + K] = __float2bfloat16(v - __bfloat162float(h));
    }
}

// ---------------- layernorm on x[0] -> split h1 ----------------
__global__ void ln1_kernel(const float* __restrict__ x,
                           const float* __restrict__ g,
                           const float* __restrict__ be) {
    __shared__ float sh1[4], sh2[4];
    int row = blockIdx.x;
    int t = threadIdx.x;  // 128
    const float* xr = x + (size_t)row * D_MOD;
    float v0 = xr[t], v1 = xr[t + 128], v2 = xr[t + 256], v3 = xr[t + 384];
    float s = v0 + v1 + v2 + v3;
    float s2 = v0 * v0 + v1 * v1 + v2 * v2 + v3 * v3;
    #pragma unroll
    for (int o = 16; o > 0; o >>= 1) {
        s += __shfl_down_sync(0xffffffffu, s, o);
        s2 += __shfl_down_sync(0xffffffffu, s2, o);
    }
    if ((t & 31) == 0) { sh1[t >> 5] = s; sh2[t >> 5] = s2; }
    __syncthreads();
    s = sh1[0] + sh1[1] + sh1[2] + sh1[3];
    s2 = sh2[0] + sh2[1] + sh2[2] + sh2[3];
    float m = s * (1.f / D_MOD);
    float rstd = rsqrtf(s2 * (1.f / D_MOD) - m * m + 1e-5f);
    __nv_bfloat16* op = g_h1s + (size_t)row * (2 * D_MOD);
    #pragma unroll
    for (int j = 0; j < 4; j++) {
        int c = t + j * 128;
        float vv = ((j == 0 ? v0 : j == 1 ? v1 : j == 2 ? v2 : v3) - m) * rstd * g[c] + be[c];
        wsplit2(&op[c], &op[D_MOD + c], vv);
    }
}

// ---------------- x2 = x + sa(broadcast); ln2 -> split ----------------
__global__ void addln2_kernel(const float* __restrict__ x,
                              const float* __restrict__ g,
                              const float* __restrict__ be) {
    __shared__ float sh1[4], sh2[4];
    int row = blockIdx.x;
    int l = row & (L_SEQ - 1);
    int t = threadIdx.x;  // 128
    const float* xr = x + (size_t)row * D_MOD;
    const float* sr = g_sa + (size_t)l * D_MOD;
    float v0 = xr[t] + sr[t];
    float v1 = xr[t + 128] + sr[t + 128];
    float v2 = xr[t + 256] + sr[t + 256];
    float v3 = xr[t + 384] + sr[t + 384];
    float* x2p = g_x2 + (size_t)row * D_MOD;
    x2p[t] = v0; x2p[t + 128] = v1; x2p[t + 256] = v2; x2p[t + 384] = v3;
    float s = v0 + v1 + v2 + v3;
    float s2 = v0 * v0 + v1 * v1 + v2 * v2 + v3 * v3;
    #pragma unroll
    for (int o = 16; o > 0; o >>= 1) {
        s += __shfl_down_sync(0xffffffffu, s, o);
        s2 += __shfl_down_sync(0xffffffffu, s2, o);
    }
    if ((t & 31) == 0) { sh1[t >> 5] = s; sh2[t >> 5] = s2; }
    __syncthreads();
    s = sh1[0] + sh1[1] + sh1[2] + sh1[3];
    s2 = sh2[0] + sh2[1] + sh2[2] + sh2[3];
    float m = s * (1.f / D_MOD);
    float rstd = rsqrtf(s2 * (1.f / D_MOD) - m * m + 1e-5f);
    __nv_bfloat16* op = g_ln2s + (size_t)row * (2 * D_MOD);
    #pragma unroll
    for (int j = 0; j < 4; j++) {
        int c = t + j * 128;
        float vv = ((j == 0 ? v0 : j == 1 ? v1 : j == 2 ? v2 : v3) - m) * rstd * g[c] + be[c];
        wsplit2(&op[c], &op[D_MOD + c], vv);
    }
}

// ---------------- column sums of q, k ----------------
__global__ void colsum_qk_kernel() {
    int c = threadIdx.x;
    int r0 = blockIdx.x * 256;
    float sq = 0.f, sk = 0.f;
    for (int r = r0; r < r0 + 256; r++) {
        sq += g_q[(size_t)r * D_MOD + c];
        sk += g_k[(size_t)r * D_MOD + c];
    }
    atomicAdd(&g_qsum[c], sq);
    atomicAdd(&g_ksum[c], sk);
}

__global__ void colsum_w_kernel() {
    int c = threadIdx.x;
    int h = c >> 6;
    int r0 = blockIdx.x * 256;
    float sq = 0.f, sk = 0.f;
    for (int r = r0; r < r0 + 256; r++) {
        float si = g_sink_in[h * L_SEQ + r];
        float so = g_src_out[h * L_SEQ + r];
        sq += g_q[(size_t)r * D_MOD + c] * si;
        sk += g_k[(size_t)r * D_MOD + c] * so;
    }
    atomicAdd(&g_qwsum[c], sq);
    atomicAdd(&g_kwsum[c], sk);
}

__global__ void stage1_kernel() {
    int w = (blockIdx.x * blockDim.x + threadIdx.x) >> 5;
    int lane = threadIdx.x & 31;
    int h = w >> 14;
    int l = w & (L_SEQ - 1);
    const float* qr = g_q + (size_t)l * D_MOD + h * DH;
    const float* kr = g_k + (size_t)l * D_MOD + h * DH;
    const float* ks = g_ksum + h * DH;
    const float* qs = g_qsum + h * DH;
    float a = (qr[lane] + EPS_F) * (ks[lane] + EPS_F)
            + (qr[lane + 32] + EPS_F) * (ks[lane + 32] + EPS_F);
    float b = (kr[lane] + EPS_F) * (qs[lane] + EPS_F)
            + (kr[lane + 32] + EPS_F) * (qs[lane + 32] + EPS_F);
    #pragma unroll
    for (int o = 16; o > 0; o >>= 1) {
        a += __shfl_down_sync(0xffffffffu, a, o);
        b += __shfl_down_sync(0xffffffffu, b, o);
    }
    if (lane == 0) {
        g_sink_in[h * L_SEQ + l] = 1.f / a;
        g_src_out[h * L_SEQ + l] = 1.f / b;
    }
}

__global__ void stage2_kernel() {
    int w = (blockIdx.x * blockDim.x + threadIdx.x) >> 5;
    int lane = threadIdx.x & 31;
    int h = w >> 14;
    int l = w & (L_SEQ - 1);
    const float* qr = g_q + (size_t)l * D_MOD + h * DH;
    const float* kr = g_k + (size_t)l * D_MOD + h * DH;
    const float* kw = g_kwsum + h * DH;
    const float* qw = g_qwsum + h * DH;
    float a = (qr[lane] + EPS_F) * (kw[lane] + EPS_F)
            + (qr[lane + 32] + EPS_F) * (kw[lane + 32] + EPS_F);
    float b = (kr[lane] + EPS_F) * (qw[lane] + EPS_F)
            + (kr[lane + 32] + EPS_F) * (qw[lane + 32] + EPS_F);
    #pragma unroll
    for (int o = 16; o > 0; o >>= 1) {
        a += __shfl_down_sync(0xffffffffu, a, o);
        b += __shfl_down_sync(0xffffffffu, b, o);
    }
    if (lane == 0) {
        g_alloc[h * L_SEQ + l] = 1.f / (1.f + expf(-a));
        g_cs[h * L_SEQ + l] = fminf(fmaxf(b, -1.f), 1.f);
    }
}

__global__ void softmax_head_kernel() {
    __shared__ float sh[32];
    int h = blockIdx.x;
    int t = threadIdx.x;  // 1024
    const float* cs = g_cs + h * L_SEQ;
    float mx = -1e30f;
    for (int i = t; i < L_SEQ; i += 1024) mx = fmaxf(mx, cs[i]);
    #pragma unroll
    for (int o = 16; o > 0; o >>= 1) mx = fmaxf(mx, __shfl_xor_sync(0xffffffffu, mx, o));
    if ((t & 31) == 0) sh[t >> 5] = mx;
    __syncthreads();
    float bm = sh[0];
    #pragma unroll
    for (int i = 1; i < 32; i++) bm = fmaxf(bm, sh[i]);
    __syncthreads();
    float se = 0.f;
    for (int i = t; i < L_SEQ; i += 1024) se += expf(cs[i] - bm);
    #pragma unroll
    for (int o = 16; o > 0; o >>= 1) se += __shfl_xor_sync(0xffffffffu, se, o);
    if ((t & 31) == 0) sh[t >> 5] = se;
    __syncthreads();
    if (t == 0) {
        float s = 0.f;
        #pragma unroll
        for (int i = 0; i < 32; i++) s += sh[i];
        g_hmax[h] = bm;
        g_hsum[h] = s;
    }
}

__global__ void kv_kernel() {
    __shared__ float sk[8][64];
    __shared__ float sv[8][64];
    int h = blockIdx.y;
    int chunk = blockIdx.x;
    int t = threadIdx.x;
    int drow = t >> 2;
    int mbase = (t & 3) << 4;
    float hmax = g_hmax[h];
    float hscale = (float)L_SEQ / g_hsum[h];
    int l0 = chunk * 512;
    float acc[16];
    #pragma unroll
    for (int j = 0; j < 16; j++) acc[j] = 0.f;
    for (int it = 0; it < 64; it++) {
        int lb = l0 + it * 8;
        #pragma unroll
        for (int j = 0; j < 4; j++) {
            int e = t + j * 256;
            if (e < 512) {
                int r = e >> 6, dd = e & 63;
                sk[r][dd] = g_k[(size_t)(lb + r) * D_MOD + h * DH + dd];
            } else {
                int e2 = e - 512;
                int r = e2 >> 6, dd = e2 & 63;
                int l = lb + r;
                float comp = expf(g_cs[h * L_SEQ + l] - hmax) * hscale;
                sv[r][dd] = g_v[(size_t)l * D_MOD + h * DH + dd] * comp;
            }
        }
        __syncthreads();
        #pragma unroll
        for (int r = 0; r < 8; r++) {
            float kd = sk[r][drow];
            #pragma unroll
            for (int j = 0; j < 16; j++) acc[j] += kd * sv[r][mbase + j];
        }
        __syncthreads();
    }
    float* kvp = g_kv + h * DH * DH + drow * DH + mbase;
    #pragma unroll
    for (int j = 0; j < 16; j++) atomicAdd(&kvp[j], acc[j]);
}

// ---------------- o = (q*sink_in) @ kv * alloc -> split bf16 ----------------
__global__ void o_kernel() {
    __shared__ float kvs[DH * DH];
    __shared__ float qs[32][64];
    int h = blockIdx.y;
    int chunk = blockIdx.x;
    int t = threadIdx.x;
    for (int e = t; e < DH * DH; e += 256) kvs[e] = g_kv[h * DH * DH + e];
    for (int e = t; e < 32 * 64; e += 256) {
        int r = e >> 6, dd = e & 63;
        int l = chunk * 32 + r;
        qs[r][dd] = g_q[(size_t)l * D_MOD + h * DH + dd] * g_sink_in[h * L_SEQ + l];
    }
    __syncthreads();
    int r = t >> 3;
    int cg = (t & 7) * 8;
    float acc[8];
    #pragma unroll
    for (int j = 0; j < 8; j++) acc[j] = 0.f;
    #pragma unroll
    for (int dd = 0; dd < 64; dd++) {
        float qv = qs[r][dd];
        #pragma unroll
        for (int j = 0; j < 8; j++) acc[j] += qv * kvs[dd * 64 + cg + j];
    }
    int l = chunk * 32 + r;
    float al = g_alloc[h * L_SEQ + l];
    __nv_bfloat16* op = g_os + (size_t)l * (2 * D_MOD) + h * DH + cg;
    #pragma unroll
    for (int j = 0; j < 8; j++) wsplit2(&op[j], &op[D_MOD + j], acc[j] * al);
}

// ---------------- mma.sync bf16 GEMM, 3-term hi/lo split ----------------
// A: [M, 2K] bf16 (hi|lo), B: [N, 2K] bf16 (hi|lo, = W^T split).
// C = A_hi B_hi^T + A_lo B_hi^T + A_hi B_lo^T  (+bias, epilogue).
// MODE 0: fp32 C=acc+bias | 1: sigmoid | 2: gelu->split bf16 Cs [row,2N] | 3: fp32 +bias+res
template <int MODE>
__global__ void __launch_bounds__(256, 2) mm_kernel(
    const __nv_bfloat16* __restrict__ A, const __nv_bfloat16* __restrict__ B,
    const float* __restrict__ bias, const float* __restrict__ res,
    float* __restrict__ Cf, __nv_bfloat16* __restrict__ Cs,
    int N, int K, int nIter, int kPerBlk) {
    extern __shared__ __align__(128) char smem[];
    uint32_t sb = sm_u32(smem);
    const int tid = threadIdx.x;
    const int wid = tid >> 5, lane = tid & 31;
    const int rowA0 = blockIdx.y * TILE, colB0 = blockIdx.x * TILE;
    const int ld = 2 * K;
    const int wm = (wid >> 2) * 64, wn = (wid & 3) * 32;

    // loader mapping: 256 threads; each thread handles one 128-row's 32B half (2x cp16)
    const int lrow = tid >> 1;
    const int loffB = (tid & 1) * 32;

    float acc[4][4][4];
    #pragma unroll
    for (int i = 0; i < 4; i++)
        #pragma unroll
        for (int j = 0; j < 4; j++)
            #pragma unroll
            for (int e = 0; e < 4; e++) acc[i][j][e] = 0.f;

    auto load_stage = [&](int slot, int it) {
        int blk = it / kPerBlk;
        int within = it - blk * kPerBlk;
        int a_x = ((blk == 1) ? K : 0) + within * KC;
        int b_x = ((blk == 2) ? K : 0) + within * KC;
        const __nv_bfloat16* Ag = A + (size_t)(rowA0 + lrow) * ld + a_x + (loffB >> 1);
        const __nv_bfloat16* Bg = B + (size_t)(colB0 + lrow) * ld + b_x + (loffB >> 1);
        uint32_t sA = sb + slot * STAGE_B + lrow * AROW_B + loffB;
        uint32_t sB = sA + HALF_STAGE;
        cp16(sA, Ag); cp16(sA + 16, Ag + 8);
        cp16(sB, Bg); cp16(sB + 16, Bg + 8);
        cp_commit();
    };

    auto compute_stage = [&](int slot) {
        uint32_t aB = sb + slot * STAGE_B;
        uint32_t bB = aB + HALF_STAGE;
        #pragma unroll
        for (int ks = 0; ks < 2; ks++) {
            uint32_t af[4][4], bfr[2][4];
            #pragma unroll
            for (int mf = 0; mf < 4; mf++)
                ldsm4(af[mf], aB + (uint32_t)((wm + mf * 16 + (lane & 15)) * AROW_B
                                              + ks * 32 + ((lane >> 4) << 4)));
            #pragma unroll
            for (int g = 0; g < 2; g++)
                ldsm4(bfr[g], bB + (uint32_t)((wn + g * 16 + (lane & 7) + ((lane & 16) >> 1)) * AROW_B
                                              + ks * 32 + ((lane & 8) << 1)));
            #pragma unroll
            for (int mf = 0; mf < 4; mf++)
                #pragma unroll
                for (int nf = 0; nf < 4; nf++)
                    mma16816(acc[mf][nf], af[mf], &bfr[nf >> 1][(nf & 1) * 2]);
        }
    };

    load_stage(0, 0);
    load_stage(1, 1);
    load_stage(2, 2);

    for (int it = 0; it < nIter; it++) {
        asm volatile("cp.async.wait_group 2;" ::: "memory");
        __syncthreads();
        compute_stage(it & 3);
        __syncthreads();
        int nx = it + 3;
        if (nx < nIter) load_stage(nx & 3, nx);
    }

    // ---- epilogue ----
    const int lm = lane >> 2;
    const int ln = (lane & 3) * 2;
    #pragma unroll
    for (int mf = 0; mf < 4; mf++) {
        #pragma unroll
        for (int nf = 0; nf < 4; nf++) {
            int m0 = rowA0 + wm + mf * 16 + lm;
            int n0 = colB0 + wn + nf * 8 + ln;
            float b0 = __ldg(&bias[n0]), b1 = __ldg(&bias[n0 + 1]);
            float f0 = acc[mf][nf][0] + b0;
            float f1 = acc[mf][nf][1] + b1;
            float f2 = acc[mf][nf][2] + b0;
            float f3 = acc[mf][nf][3] + b1;
            if (MODE == 1) {
                f0 = 1.f / (1.f + expf(-f0)); f1 = 1.f / (1.f + expf(-f1));
                f2 = 1.f / (1.f + expf(-f2)); f3 = 1.f / (1.f + expf(-f3));
            } else if (MODE == 2) {
                f0 = 0.5f * f0 * (1.f + erff(f0 * 0.70710678118654752f));
                f1 = 0.5f * f1 * (1.f + erff(f1 * 0.70710678118654752f));
                f2 = 0.5f * f2 * (1.f + erff(f2 * 0.70710678118654752f));
                f3 = 0.5f * f3 * (1.f + erff(f3 * 0.70710678118654752f));
            } else if (MODE == 3) {
                float2 r0 = *(const float2*)(res + (size_t)m0 * N + n0);
                float2 r1 = *(const float2*)(res + (size_t)(m0 + 8) * N + n0);
                f0 += r0.x; f1 += r0.y; f2 += r1.x; f3 += r1.y;
            }
            if (MODE == 2) {
                __nv_bfloat16* hp0 = Cs + (size_t)m0 * (2 * N) + n0;
                __nv_bfloat16* hp1 = Cs + (size_t)(m0 + 8) * (2 * N) + n0;
                __nv_bfloat162 hv, lv;
                hv.x = __float2bfloat16(f0);
                hv.y = __float2bfloat16(f1);
                lv.x = __float2bfloat16(f0 - __bfloat162float(hv.x));
                lv.y = __float2bfloat16(f1 - __bfloat162float(hv.y));
                *(__nv_bfloat162*)hp0 = hv;
                *(__nv_bfloat162*)(hp0 + N) = lv;
                hv.x = __float2bfloat16(f2);
                hv.y = __float2bfloat16(f3);
                lv.x = __float2bfloat16(f2 - __bfloat162float(hv.x));
                lv.y = __float2bfloat16(f3 - __bfloat162float(hv.y));
                *(__nv_bfloat162*)hp1 = hv;
                *(__nv_bfloat162*)(hp1 + N) = lv;
            } else {
                float2 v0; v0.x = f0; v0.y = f1;
                float2 v1; v1.x = f2; v1.y = f3;
                *(float2*)(Cf + (size_t)m0 * N + n0) = v0;
                *(float2*)(Cf + (size_t)(m0 + 8) * N + n0) = v1;
            }
        }
    }
}

// ---------------- launcher ----------------
extern "C" void kernel_launch(void* const* d_in, const int* in_sizes, int n_in,
                              void* d_out, int out_size) {
    (void)in_sizes; (void)n_in; (void)out_size;
    const float* x   = (const float*)d_in[0];
    const float* Wq  = (const float*)d_in[1];
    const float* bq  = (const float*)d_in[2];
    const float* Wk  = (const float*)d_in[3];
    const float* bk  = (const float*)d_in[4];
    const float* Wv  = (const float*)d_in[5];
    const float* bv  = (const float*)d_in[6];
    const float* Wo  = (const float*)d_in[7];
    const float* bo  = (const float*)d_in[8];
    const float* W1  = (const float*)d_in[9];
    const float* b1  = (const float*)d_in[10];
    const float* W2  = (const float*)d_in[11];
    const float* b2  = (const float*)d_in[12];
    const float* g1  = (const float*)d_in[13];
    const float* be1 = (const float*)d_in[14];
    const float* g2  = (const float*)d_in[15];
    const float* be2 = (const float*)d_in[16];
    float* out = (float*)d_out;

    __nv_bfloat16 *p_h1s, *p_os, *p_ln2s, *p_ts, *p_Wqs, *p_Wks, *p_Wvs, *p_Wos, *p_W1s, *p_W2s;
    float *p_q, *p_k, *p_v, *p_sa, *p_x2;
    cudaGetSymbolAddress((void**)&p_h1s, g_h1s);
    cudaGetSymbolAddress((void**)&p_os, g_os);
    cudaGetSymbolAddress((void**)&p_ln2s, g_ln2s);
    cudaGetSymbolAddress((void**)&p_ts, g_ts);
    cudaGetSymbolAddress((void**)&p_Wqs, g_Wqs);
    cudaGetSymbolAddress((void**)&p_Wks, g_Wks);
    cudaGetSymbolAddress((void**)&p_Wvs, g_Wvs);
    cudaGetSymbolAddress((void**)&p_Wos, g_Wos);
    cudaGetSymbolAddress((void**)&p_W1s, g_W1s);
    cudaGetSymbolAddress((void**)&p_W2s, g_W2s);
    cudaGetSymbolAddress((void**)&p_q, g_q);
    cudaGetSymbolAddress((void**)&p_k, g_k);
    cudaGetSymbolAddress((void**)&p_v, g_v);
    cudaGetSymbolAddress((void**)&p_sa, g_sa);
    cudaGetSymbolAddress((void**)&p_x2, g_x2);

    cudaFuncSetAttribute(mm_kernel<0>, cudaFuncAttributeMaxDynamicSharedMemorySize, SMEM_SZ);
    cudaFuncSetAttribute(mm_kernel<1>, cudaFuncAttributeMaxDynamicSharedMemorySize, SMEM_SZ);
    cudaFuncSetAttribute(mm_kernel<2>, cudaFuncAttributeMaxDynamicSharedMemorySize, SMEM_SZ);
    cudaFuncSetAttribute(mm_kernel<3>, cudaFuncAttributeMaxDynamicSharedMemorySize, SMEM_SZ);

    zero_acc_kernel<<<128, 256>>>();

    dim3 wblk(32, 8);
    wsplit_kernel<<<dim3(D_MOD / 32, D_MOD / 32), wblk>>>(Wq, p_Wqs, D_MOD, D_MOD);
    wsplit_kernel<<<dim3(D_MOD / 32, D_MOD / 32), wblk>>>(Wk, p_Wks, D_MOD, D_MOD);
    wsplit_kernel<<<dim3(D_MOD / 32, D_MOD / 32), wblk>>>(Wv, p_Wvs, D_MOD, D_MOD);
    wsplit_kernel<<<dim3(D_MOD / 32, D_MOD / 32), wblk>>>(Wo, p_Wos, D_MOD, D_MOD);
    wsplit_kernel<<<dim3(FF / 32, D_MOD / 32), wblk>>>(W1, p_W1s, D_MOD, FF);
    wsplit_kernel<<<dim3(D_MOD / 32, FF / 32), wblk>>>(W2, p_W2s, FF, D_MOD);

    ln1_kernel<<<L_SEQ, 128>>>(x, g1, be1);

    // K=512: nIter = 3*512/32 = 48, kPerBlk = 16
    dim3 gqkv(D_MOD / TILE, L_SEQ / TILE);  // (4, 128)
    mm_kernel<1><<<gqkv, 256, SMEM_SZ>>>(p_h1s, p_Wqs, bq, nullptr, p_q, nullptr, D_MOD, D_MOD, 48, 16);
    mm_kernel<1><<<gqkv, 256, SMEM_SZ>>>(p_h1s, p_Wks, bk, nullptr, p_k, nullptr, D_MOD, D_MOD, 48, 16);
    mm_kernel<0><<<gqkv, 256, SMEM_SZ>>>(p_h1s, p_Wvs, bv, nullptr, p_v, nullptr, D_MOD, D_MOD, 48, 16);

    colsum_qk_kernel<<<64, 512>>>();
    stage1_kernel<<<(NH * L_SEQ) / 8, 256>>>();
    colsum_w_kernel<<<64, 512>>>();
    stage2_kernel<<<(NH * L_SEQ) / 8, 256>>>();
    softmax_head_kernel<<<NH, 1024>>>();
    kv_kernel<<<dim3(32, NH), 256>>>();
    o_kernel<<<dim3(L_SEQ / 32, NH), 256>>>();

    mm_kernel<0><<<gqkv, 256, SMEM_SZ>>>(p_os, p_Wos, bo, nullptr, p_sa, nullptr, D_MOD, D_MOD, 48, 16);

    addln2_kernel<<<BATCH * L_SEQ, 128>>>(x, g2, be2);

    dim3 gf1(FF / TILE, (BATCH * L_SEQ) / TILE);    // (16, 256)
    mm_kernel<2><<<gf1, 256, SMEM_SZ>>>(p_ln2s, p_W1s, b1, nullptr, nullptr, p_ts, FF, D_MOD, 48, 16);

    // K=2048: nIter = 3*2048/32 = 192, kPerBlk = 64
    dim3 gf2(D_MOD / TILE, (BATCH * L_SEQ) / TILE); // (4, 256)
    mm_kernel<3><<<gf2, 256, SMEM_SZ>>>(p_ts, p_W2s, b2, p_x2, out, nullptr, D_MOD, FF, 192, 64);
}

// round 4
// speedup vs baseline: 3.5275x; 2.0724x over previous
#include <cuda_runtime.h>
#include <cuda_fp16.h>
#include <math.h>
#include <stdint.h>

// ---------------- problem constants ----------------
#define L_SEQ 16384
#define D_MOD 512
#define NH 8
#define DH 64
#define FF 2048
#define BATCH 2
#define EPS_F 1e-6f

// GEMM tiling
#define TILE 128
#define KC 32
#define AROW_B 80                       // padded smem row bytes (32 fp16 data + 16B pad)
#define HALF_STAGE (128 * AROW_B)       // 10240
#define STAGE_B (2 * HALF_STAGE)        // 20480 (A + B)
#define SMEM_SZ (4 * STAGE_B)           // 81920

// ---------------- scratch (static device globals; no allocation) ----------------
__device__ __align__(128) __half g_h1h[L_SEQ * D_MOD];            // ln1(x[0]) fp16
__device__ __align__(128) __half g_oh [L_SEQ * D_MOD];            // attn out fp16
__device__ __align__(128) __half g_ln2h[BATCH * L_SEQ * D_MOD];   // ln2 fp16
__device__ __align__(128) __half g_th [(size_t)BATCH * L_SEQ * FF]; // gelu(ffn1) fp16
__device__ __align__(128) __half g_Wqh[D_MOD * D_MOD];            // W^T fp16
__device__ __align__(128) __half g_Wkh[D_MOD * D_MOD];
__device__ __align__(128) __half g_Wvh[D_MOD * D_MOD];
__device__ __align__(128) __half g_Woh[D_MOD * D_MOD];
__device__ __align__(128) __half g_W1h[FF * D_MOD];
__device__ __align__(128) __half g_W2h[D_MOD * FF];

__device__ __align__(16) float g_q[L_SEQ * D_MOD];
__device__ __align__(16) float g_k[L_SEQ * D_MOD];
__device__ __align__(16) float g_v[L_SEQ * D_MOD];
__device__ __align__(16) float g_sa[L_SEQ * D_MOD];
__device__ __align__(16) float g_x2[BATCH * L_SEQ * D_MOD];

__device__ float g_ksum[D_MOD], g_qsum[D_MOD];
__device__ float g_kwsum[D_MOD], g_qwsum[D_MOD];
__device__ float g_sink_in[NH * L_SEQ];
__device__ float g_src_out[NH * L_SEQ];
__device__ float g_alloc[NH * L_SEQ];
__device__ float g_cs[NH * L_SEQ];
__device__ float g_hmax[NH], g_hsum[NH];
__device__ float g_kv[NH * DH * DH];

// ---------------- PTX helpers (baseline sm_80+ only) ----------------
__device__ __forceinline__ uint32_t sm_u32(const void* p) {
    uint32_t a;
    asm("{ .reg .u64 t; cvta.to.shared.u64 t, %1; cvt.u32.u64 %0, t; }" : "=r"(a) : "l"(p));
    return a;
}
__device__ __forceinline__ void cp16(uint32_t s, const void* g) {
    asm volatile("cp.async.cg.shared.global [%0], [%1], 16;" :: "r"(s), "l"(g));
}
__device__ __forceinline__ void cp_commit() {
    asm volatile("cp.async.commit_group;" ::: "memory");
}
__device__ __forceinline__ void ldsm4(uint32_t* r, uint32_t addr) {
    asm volatile("ldmatrix.sync.aligned.m8n8.x4.shared.b16 {%0,%1,%2,%3}, [%4];"
                 : "=r"(r[0]), "=r"(r[1]), "=r"(r[2]), "=r"(r[3]) : "r"(addr));
}
__device__ __forceinline__ void mma16816(float* d, const uint32_t* a, const uint32_t* b) {
    asm volatile(
        "mma.sync.aligned.m16n8k16.row.col.f32.f16.f16.f32 "
        "{%0,%1,%2,%3}, {%4,%5,%6,%7}, {%8,%9}, {%0,%1,%2,%3};"
        : "+f"(d[0]), "+f"(d[1]), "+f"(d[2]), "+f"(d[3])
        : "r"(a[0]), "r"(a[1]), "r"(a[2]), "r"(a[3]), "r"(b[0]), "r"(b[1]));
}

// ---------------- zero accumulators ----------------
__global__ void zero_acc_kernel() {
    int t = blockIdx.x * blockDim.x + threadIdx.x;
    if (t < D_MOD) { g_ksum[t] = 0.f; g_qsum[t] = 0.f; g_kwsum[t] = 0.f; g_qwsum[t] = 0.f; }
    if (t < NH * DH * DH) g_kv[t] = 0.f;
}

// ---------------- weight transpose+cast: W[K,N] -> Wt[N,K] fp16 ----------------
__global__ void wsplit_kernel(const float* __restrict__ W, __half* __restrict__ Wt,
                              int K, int N) {
    __shared__ float tile[32][33];
    int k0 = blockIdx.y * 32, n0 = blockIdx.x * 32;
    int tx = threadIdx.x, ty = threadIdx.y;  // 32 x 8
    for (int i = ty; i < 32; i += 8) tile[i][tx] = W[(size_t)(k0 + i) * N + n0 + tx];
    __syncthreads();
    for (int i = ty; i < 32; i += 8)
        Wt[(size_t)(n0 + i) * K + k0 + tx] = __float2half_rn(tile[tx][i]);
}

// ---------------- layernorm on x[0] -> fp16 h1 ----------------
__global__ void ln1_kernel(const float* __restrict__ x,
                           const float* __restrict__ g,
                           const float* __restrict__ be) {
    __shared__ float sh1[4], sh2[4];
    int row = blockIdx.x;
    int t = threadIdx.x;  // 128
    const float* xr = x + (size_t)row * D_MOD;
    float v0 = xr[t], v1 = xr[t + 128], v2 = xr[t + 256], v3 = xr[t + 384];
    float s = v0 + v1 + v2 + v3;
    float s2 = v0 * v0 + v1 * v1 + v2 * v2 + v3 * v3;
    #pragma unroll
    for (int o = 16; o > 0; o >>= 1) {
        s += __shfl_down_sync(0xffffffffu, s, o);
        s2 += __shfl_down_sync(0xffffffffu, s2, o);
    }
    if ((t & 31) == 0) { sh1[t >> 5] = s; sh2[t >> 5] = s2; }
    __syncthreads();
    s = sh1[0] + sh1[1] + sh1[2] + sh1[3];
    s2 = sh2[0] + sh2[1] + sh2[2] + sh2[3];
    float m = s * (1.f / D_MOD);
    float rstd = rsqrtf(s2 * (1.f / D_MOD) - m * m + 1e-5f);
    __half* op = g_h1h + (size_t)row * D_MOD;
    op[t]       = __float2half_rn((v0 - m) * rstd * g[t]       + be[t]);
    op[t + 128] = __float2half_rn((v1 - m) * rstd * g[t + 128] + be[t + 128]);
    op[t + 256] = __float2half_rn((v2 - m) * rstd * g[t + 256] + be[t + 256]);
    op[t + 384] = __float2half_rn((v3 - m) * rstd * g[t + 384] + be[t + 384]);
}

// ---------------- x2 = x + sa(broadcast); ln2 -> fp16 ----------------
__global__ void addln2_kernel(const float* __restrict__ x,
                              const float* __restrict__ g,
                              const float* __restrict__ be) {
    __shared__ float sh1[4], sh2[4];
    int row = blockIdx.x;
    int l = row & (L_SEQ - 1);
    int t = threadIdx.x;  // 128
    const float* xr = x + (size_t)row * D_MOD;
    const float* sr = g_sa + (size_t)l * D_MOD;
    float v0 = xr[t] + sr[t];
    float v1 = xr[t + 128] + sr[t + 128];
    float v2 = xr[t + 256] + sr[t + 256];
    float v3 = xr[t + 384] + sr[t + 384];
    float* x2p = g_x2 + (size_t)row * D_MOD;
    x2p[t] = v0; x2p[t + 128] = v1; x2p[t + 256] = v2; x2p[t + 384] = v3;
    float s = v0 + v1 + v2 + v3;
    float s2 = v0 * v0 + v1 * v1 + v2 * v2 + v3 * v3;
    #pragma unroll
    for (int o = 16; o > 0; o >>= 1) {
        s += __shfl_down_sync(0xffffffffu, s, o);
        s2 += __shfl_down_sync(0xffffffffu, s2, o);
    }
    if ((t & 31) == 0) { sh1[t >> 5] = s; sh2[t >> 5] = s2; }
    __syncthreads();
    s = sh1[0] + sh1[1] + sh1[2] + sh1[3];
    s2 = sh2[0] + sh2[1] + sh2[2] + sh2[3];
    float m = s * (1.f / D_MOD);
    float rstd = rsqrtf(s2 * (1.f / D_MOD) - m * m + 1e-5f);
    __half* op = g_ln2h + (size_t)row * D_MOD;
    op[t]       = __float2half_rn((v0 - m) * rstd * g[t]       + be[t]);
    op[t + 128] = __float2half_rn((v1 - m) * rstd * g[t + 128] + be[t + 128]);
    op[t + 256] = __float2half_rn((v2 - m) * rstd * g[t + 256] + be[t + 256]);
    op[t + 384] = __float2half_rn((v3 - m) * rstd * g[t + 384] + be[t + 384]);
}

// ---------------- column sums of q, k ----------------
__global__ void colsum_qk_kernel() {
    int c = threadIdx.x;
    int r0 = blockIdx.x * 256;
    float sq = 0.f, sk = 0.f;
    for (int r = r0; r < r0 + 256; r++) {
        sq += g_q[(size_t)r * D_MOD + c];
        sk += g_k[(size_t)r * D_MOD + c];
    }
    atomicAdd(&g_qsum[c], sq);
    atomicAdd(&g_ksum[c], sk);
}

__global__ void colsum_w_kernel() {
    int c = threadIdx.x;
    int h = c >> 6;
    int r0 = blockIdx.x * 256;
    float sq = 0.f, sk = 0.f;
    for (int r = r0; r < r0 + 256; r++) {
        float si = g_sink_in[h * L_SEQ + r];
        float so = g_src_out[h * L_SEQ + r];
        sq += g_q[(size_t)r * D_MOD + c] * si;
        sk += g_k[(size_t)r * D_MOD + c] * so;
    }
    atomicAdd(&g_qwsum[c], sq);
    atomicAdd(&g_kwsum[c], sk);
}

__global__ void stage1_kernel() {
    int w = (blockIdx.x * blockDim.x + threadIdx.x) >> 5;
    int lane = threadIdx.x & 31;
    int h = w >> 14;
    int l = w & (L_SEQ - 1);
    const float* qr = g_q + (size_t)l * D_MOD + h * DH;
    const float* kr = g_k + (size_t)l * D_MOD + h * DH;
    const float* ks = g_ksum + h * DH;
    const float* qs = g_qsum + h * DH;
    float a = (qr[lane] + EPS_F) * (ks[lane] + EPS_F)
            + (qr[lane + 32] + EPS_F) * (ks[lane + 32] + EPS_F);
    float b = (kr[lane] + EPS_F) * (qs[lane] + EPS_F)
            + (kr[lane + 32] + EPS_F) * (qs[lane + 32] + EPS_F);
    #pragma unroll
    for (int o = 16; o > 0; o >>= 1) {
        a += __shfl_down_sync(0xffffffffu, a, o);
        b += __shfl_down_sync(0xffffffffu, b, o);
    }
    if (lane == 0) {
        g_sink_in[h * L_SEQ + l] = 1.f / a;
        g_src_out[h * L_SEQ + l] = 1.f / b;
    }
}

__global__ void stage2_kernel() {
    int w = (blockIdx.x * blockDim.x + threadIdx.x) >> 5;
    int lane = threadIdx.x & 31;
    int h = w >> 14;
    int l = w & (L_SEQ - 1);
    const float* qr = g_q + (size_t)l * D_MOD + h * DH;
    const float* kr = g_k + (size_t)l * D_MOD + h * DH;
    const float* kw = g_kwsum + h * DH;
    const float* qw = g_qwsum + h * DH;
    float a = (qr[lane] + EPS_F) * (kw[lane] + EPS_F)
            + (qr[lane + 32] + EPS_F) * (kw[lane + 32] + EPS_F);
    float b = (kr[lane] + EPS_F) * (qw[lane] + EPS_F)
            + (kr[lane + 32] + EPS_F) * (qw[lane + 32] + EPS_F);
    #pragma unroll
    for (int o = 16; o > 0; o >>= 1) {
        a += __shfl_down_sync(0xffffffffu, a, o);
        b += __shfl_down_sync(0xffffffffu, b, o);
    }
    if (lane == 0) {
        g_alloc[h * L_SEQ + l] = 1.f / (1.f + expf(-a));
        g_cs[h * L_SEQ + l] = fminf(fmaxf(b, -1.f), 1.f);
    }
}

__global__ void softmax_head_kernel() {
    __shared__ float sh[32];
    int h = blockIdx.x;
    int t = threadIdx.x;  // 1024
    const float* cs = g_cs + h * L_SEQ;
    float mx = -1e30f;
    for (int i = t; i < L_SEQ; i += 1024) mx = fmaxf(mx, cs[i]);
    #pragma unroll
    for (int o = 16; o > 0; o >>= 1) mx = fmaxf(mx, __shfl_xor_sync(0xffffffffu, mx, o));
    if ((t & 31) == 0) sh[t >> 5] = mx;
    __syncthreads();
    float bm = sh[0];
    #pragma unroll
    for (int i = 1; i < 32; i++) bm = fmaxf(bm, sh[i]);
    __syncthreads();
    float se = 0.f;
    for (int i = t; i < L_SEQ; i += 1024) se += expf(cs[i] - bm);
    #pragma unroll
    for (int o = 16; o > 0; o >>= 1) se += __shfl_xor_sync(0xffffffffu, se, o);
    if ((t & 31) == 0) sh[t >> 5] = se;
    __syncthreads();
    if (t == 0) {
        float s = 0.f;
        #pragma unroll
        for (int i = 0; i < 32; i++) s += sh[i];
        g_hmax[h] = bm;
        g_hsum[h] = s;
    }
}

__global__ void kv_kernel() {
    __shared__ float sk[8][64];
    __shared__ float sv[8][64];
    int h = blockIdx.y;
    int chunk = blockIdx.x;
    int t = threadIdx.x;
    int drow = t >> 2;
    int mbase = (t & 3) << 4;
    float hmax = g_hmax[h];
    float hscale = (float)L_SEQ / g_hsum[h];
    int l0 = chunk * 512;
    float acc[16];
    #pragma unroll
    for (int j = 0; j < 16; j++) acc[j] = 0.f;
    for (int it = 0; it < 64; it++) {
        int lb = l0 + it * 8;
        #pragma unroll
        for (int j = 0; j < 4; j++) {
            int e = t + j * 256;
            if (e < 512) {
                int r = e >> 6, dd = e & 63;
                sk[r][dd] = g_k[(size_t)(lb + r) * D_MOD + h * DH + dd];
            } else {
                int e2 = e - 512;
                int r = e2 >> 6, dd = e2 & 63;
                int l = lb + r;
                float comp = expf(g_cs[h * L_SEQ + l] - hmax) * hscale;
                sv[r][dd] = g_v[(size_t)l * D_MOD + h * DH + dd] * comp;
            }
        }
        __syncthreads();
        #pragma unroll
        for (int r = 0; r < 8; r++) {
            float kd = sk[r][drow];
            #pragma unroll
            for (int j = 0; j < 16; j++) acc[j] += kd * sv[r][mbase + j];
        }
        __syncthreads();
    }
    float* kvp = g_kv + h * DH * DH + drow * DH + mbase;
    #pragma unroll
    for (int j = 0; j < 16; j++) atomicAdd(&kvp[j], acc[j]);
}

// ---------------- o = (q*sink_in) @ kv * alloc -> fp16 ----------------
__global__ void o_kernel() {
    __shared__ float kvs[DH * DH];
    __shared__ float qs[32][64];
    int h = blockIdx.y;
    int chunk = blockIdx.x;
    int t = threadIdx.x;
    for (int e = t; e < DH * DH; e += 256) kvs[e] = g_kv[h * DH * DH + e];
    for (int e = t; e < 32 * 64; e += 256) {
        int r = e >> 6, dd = e & 63;
        int l = chunk * 32 + r;
        qs[r][dd] = g_q[(size_t)l * D_MOD + h * DH + dd] * g_sink_in[h * L_SEQ + l];
    }
    __syncthreads();
    int r = t >> 3;
    int cg = (t & 7) * 8;
    float acc[8];
    #pragma unroll
    for (int j = 0; j < 8; j++) acc[j] = 0.f;
    #pragma unroll
    for (int dd = 0; dd < 64; dd++) {
        float qv = qs[r][dd];
        #pragma unroll
        for (int j = 0; j < 8; j++) acc[j] += qv * kvs[dd * 64 + cg + j];
    }
    int l = chunk * 32 + r;
    float al = g_alloc[h * L_SEQ + l];
    __half* op = g_oh + (size_t)l * D_MOD + h * DH + cg;
    #pragma unroll
    for (int j = 0; j < 8; j++) op[j] = __float2half_rn(acc[j] * al);
}

// ---------------- mma.sync fp16 GEMM (single pass, fp32 accumulate) ----------------
// A: [M,K] fp16 row-major, B: [N,K] fp16 (W^T).
// MODE 0: fp32 C=acc+bias | 1: sigmoid | 2: gelu -> fp16 Cs | 3: fp32 +bias+res
template <int MODE>
__global__ void __launch_bounds__(256, 2) mm_kernel(
    const __half* __restrict__ A, const __half* __restrict__ B,
    const float* __restrict__ bias, const float* __restrict__ res,
    float* __restrict__ Cf, __half* __restrict__ Cs,
    int N, int K, int nIter) {
    extern __shared__ __align__(128) char smem[];
    uint32_t sb = sm_u32(smem);
    const int tid = threadIdx.x;
    const int wid = tid >> 5, lane = tid & 31;
    const int rowA0 = blockIdx.y * TILE, colB0 = blockIdx.x * TILE;
    const int wm = (wid >> 2) * 64, wn = (wid & 3) * 32;

    const int lrow = tid >> 1;
    const int loffB = (tid & 1) * 32;

    float acc[4][4][4];
    #pragma unroll
    for (int i = 0; i < 4; i++)
        #pragma unroll
        for (int j = 0; j < 4; j++)
            #pragma unroll
            for (int e = 0; e < 4; e++) acc[i][j][e] = 0.f;

    auto load_stage = [&](int slot, int it) {
        const __half* Ag = A + (size_t)(rowA0 + lrow) * K + it * KC + (loffB >> 1);
        const __half* Bg = B + (size_t)(colB0 + lrow) * K + it * KC + (loffB >> 1);
        uint32_t sA = sb + slot * STAGE_B + lrow * AROW_B + loffB;
        uint32_t sB = sA + HALF_STAGE;
        cp16(sA, Ag); cp16(sA + 16, Ag + 8);
        cp16(sB, Bg); cp16(sB + 16, Bg + 8);
        cp_commit();
    };

    auto compute_stage = [&](int slot) {
        uint32_t aB = sb + slot * STAGE_B;
        uint32_t bB = aB + HALF_STAGE;
        #pragma unroll
        for (int ks = 0; ks < 2; ks++) {
            uint32_t af[4][4], bfr[2][4];
            #pragma unroll
            for (int mf = 0; mf < 4; mf++)
                ldsm4(af[mf], aB + (uint32_t)((wm + mf * 16 + (lane & 15)) * AROW_B
                                              + ks * 32 + ((lane >> 4) << 4)));
            #pragma unroll
            for (int g = 0; g < 2; g++)
                ldsm4(bfr[g], bB + (uint32_t)((wn + g * 16 + (lane & 7) + ((lane & 16) >> 1)) * AROW_B
                                              + ks * 32 + ((lane & 8) << 1)));
            #pragma unroll
            for (int mf = 0; mf < 4; mf++)
                #pragma unroll
                for (int nf = 0; nf < 4; nf++)
                    mma16816(acc[mf][nf], af[mf], &bfr[nf >> 1][(nf & 1) * 2]);
        }
    };

    load_stage(0, 0);
    load_stage(1, 1);
    load_stage(2, 2);

    for (int it = 0; it < nIter; it++) {
        asm volatile("cp.async.wait_group 2;" ::: "memory");
        __syncthreads();
        compute_stage(it & 3);
        __syncthreads();
        int nx = it + 3;
        if (nx < nIter) load_stage(nx & 3, nx);
    }

    // ---- epilogue ----
    const int lm = lane >> 2;
    const int ln = (lane & 3) * 2;
    #pragma unroll
    for (int mf = 0; mf < 4; mf++) {
        #pragma unroll
        for (int nf = 0; nf < 4; nf++) {
            int m0 = rowA0 + wm + mf * 16 + lm;
            int n0 = colB0 + wn + nf * 8 + ln;
            float b0 = __ldg(&bias[n0]), b1 = __ldg(&bias[n0 + 1]);
            float f0 = acc[mf][nf][0] + b0;
            float f1 = acc[mf][nf][1] + b1;
            float f2 = acc[mf][nf][2] + b0;
            float f3 = acc[mf][nf][3] + b1;
            if (MODE == 1) {
                f0 = 1.f / (1.f + expf(-f0)); f1 = 1.f / (1.f + expf(-f1));
                f2 = 1.f / (1.f + expf(-f2)); f3 = 1.f / (1.f + expf(-f3));
            } else if (MODE == 2) {
                f0 = 0.5f * f0 * (1.f + erff(f0 * 0.70710678118654752f));
                f1 = 0.5f * f1 * (1.f + erff(f1 * 0.70710678118654752f));
                f2 = 0.5f * f2 * (1.f + erff(f2 * 0.70710678118654752f));
                f3 = 0.5f * f3 * (1.f + erff(f3 * 0.70710678118654752f));
            } else if (MODE == 3) {
                float2 r0 = *(const float2*)(res + (size_t)m0 * N + n0);
                float2 r1 = *(const float2*)(res + (size_t)(m0 + 8) * N + n0);
                f0 += r0.x; f1 += r0.y; f2 += r1.x; f3 += r1.y;
            }
            if (MODE == 2) {
                __half2 h0; h0.x = __float2half_rn(f0); h0.y = __float2half_rn(f1);
                __half2 h1; h1.x = __float2half_rn(f2); h1.y = __float2half_rn(f3);
                *(__half2*)(Cs + (size_t)m0 * N + n0) = h0;
                *(__half2*)(Cs + (size_t)(m0 + 8) * N + n0) = h1;
            } else {
                float2 v0; v0.x = f0; v0.y = f1;
                float2 v1; v1.x = f2; v1.y = f3;
                *(float2*)(Cf + (size_t)m0 * N + n0) = v0;
                *(float2*)(Cf + (size_t)(m0 + 8) * N + n0) = v1;
            }
        }
    }
}

// ---------------- launcher ----------------
extern "C" void kernel_launch(void* const* d_in, const int* in_sizes, int n_in,
                              void* d_out, int out_size) {
    (void)in_sizes; (void)n_in; (void)out_size;
    const float* x   = (const float*)d_in[0];
    const float* Wq  = (const float*)d_in[1];
    const float* bq  = (const float*)d_in[2];
    const float* Wk  = (const float*)d_in[3];
    const float* bk  = (const float*)d_in[4];
    const float* Wv  = (const float*)d_in[5];
    const float* bv  = (const float*)d_in[6];
    const float* Wo  = (const float*)d_in[7];
    const float* bo  = (const float*)d_in[8];
    const float* W1  = (const float*)d_in[9];
    const float* b1  = (const float*)d_in[10];
    const float* W2  = (const float*)d_in[11];
    const float* b2  = (const float*)d_in[12];
    const float* g1  = (const float*)d_in[13];
    const float* be1 = (const float*)d_in[14];
    const float* g2  = (const float*)d_in[15];
    const float* be2 = (const float*)d_in[16];
    float* out = (float*)d_out;

    __half *p_h1h, *p_oh, *p_ln2h, *p_th, *p_Wqh, *p_Wkh, *p_Wvh, *p_Woh, *p_W1h, *p_W2h;
    float *p_q, *p_k, *p_v, *p_sa, *p_x2;
    cudaGetSymbolAddress((void**)&p_h1h, g_h1h);
    cudaGetSymbolAddress((void**)&p_oh, g_oh);
    cudaGetSymbolAddress((void**)&p_ln2h, g_ln2h);
    cudaGetSymbolAddress((void**)&p_th, g_th);
    cudaGetSymbolAddress((void**)&p_Wqh, g_Wqh);
    cudaGetSymbolAddress((void**)&p_Wkh, g_Wkh);
    cudaGetSymbolAddress((void**)&p_Wvh, g_Wvh);
    cudaGetSymbolAddress((void**)&p_Woh, g_Woh);
    cudaGetSymbolAddress((void**)&p_W1h, g_W1h);
    cudaGetSymbolAddress((void**)&p_W2h, g_W2h);
    cudaGetSymbolAddress((void**)&p_q, g_q);
    cudaGetSymbolAddress((void**)&p_k, g_k);
    cudaGetSymbolAddress((void**)&p_v, g_v);
    cudaGetSymbolAddress((void**)&p_sa, g_sa);
    cudaGetSymbolAddress((void**)&p_x2, g_x2);

    cudaFuncSetAttribute(mm_kernel<0>, cudaFuncAttributeMaxDynamicSharedMemorySize, SMEM_SZ);
    cudaFuncSetAttribute(mm_kernel<1>, cudaFuncAttributeMaxDynamicSharedMemorySize, SMEM_SZ);
    cudaFuncSetAttribute(mm_kernel<2>, cudaFuncAttributeMaxDynamicSharedMemorySize, SMEM_SZ);
    cudaFuncSetAttribute(mm_kernel<3>, cudaFuncAttributeMaxDynamicSharedMemorySize, SMEM_SZ);

    zero_acc_kernel<<<128, 256>>>();

    dim3 wblk(32, 8);
    wsplit_kernel<<<dim3(D_MOD / 32, D_MOD / 32), wblk>>>(Wq, p_Wqh, D_MOD, D_MOD);
    wsplit_kernel<<<dim3(D_MOD / 32, D_MOD / 32), wblk>>>(Wk, p_Wkh, D_MOD, D_MOD);
    wsplit_kernel<<<dim3(D_MOD / 32, D_MOD / 32), wblk>>>(Wv, p_Wvh, D_MOD, D_MOD);
    wsplit_kernel<<<dim3(D_MOD / 32, D_MOD / 32), wblk>>>(Wo, p_Woh, D_MOD, D_MOD);
    wsplit_kernel<<<dim3(FF / 32, D_MOD / 32), wblk>>>(W1, p_W1h, D_MOD, FF);
    wsplit_kernel<<<dim3(D_MOD / 32, FF / 32), wblk>>>(W2, p_W2h, FF, D_MOD);

    ln1_kernel<<<L_SEQ, 128>>>(x, g1, be1);

    // K=512: nIter = 16
    dim3 gqkv(D_MOD / TILE, L_SEQ / TILE);  // (4, 128)
    mm_kernel<1><<<gqkv, 256, SMEM_SZ>>>(p_h1h, p_Wqh, bq, nullptr, p_q, nullptr, D_MOD, D_MOD, 16);
    mm_kernel<1><<<gqkv, 256, SMEM_SZ>>>(p_h1h, p_Wkh, bk, nullptr, p_k, nullptr, D_MOD, D_MOD, 16);
    mm_kernel<0><<<gqkv, 256, SMEM_SZ>>>(p_h1h, p_Wvh, bv, nullptr, p_v, nullptr, D_MOD, D_MOD, 16);

    colsum_qk_kernel<<<64, 512>>>();
    stage1_kernel<<<(NH * L_SEQ) / 8, 256>>>();
    colsum_w_kernel<<<64, 512>>>();
    stage2_kernel<<<(NH * L_SEQ) / 8, 256>>>();
    softmax_head_kernel<<<NH, 1024>>>();
    kv_kernel<<<dim3(32, NH), 256>>>();
    o_kernel<<<dim3(L_SEQ / 32, NH), 256>>>();

    mm_kernel<0><<<gqkv, 256, SMEM_SZ>>>(p_oh, p_Woh, bo, nullptr, p_sa, nullptr, D_MOD, D_MOD, 16);

    addln2_kernel<<<BATCH * L_SEQ, 128>>>(x, g2, be2);

    dim3 gf1(FF / TILE, (BATCH * L_SEQ) / TILE);    // (16, 256)
    mm_kernel<2><<<gf1, 256, SMEM_SZ>>>(p_ln2h, p_W1h, b1, nullptr, nullptr, p_th, FF, D_MOD, 16);

    // K=2048: nIter = 64
    dim3 gf2(D_MOD / TILE, (BATCH * L_SEQ) / TILE); // (4, 256)
    mm_kernel<3><<<gf2, 256, SMEM_SZ>>>(p_th, p_W2h, b2, p_x2, out, nullptr, D_MOD, FF, 64);
}

// round 5
// speedup vs baseline: 3.5337x; 1.0018x over previous
#include <cuda_runtime.h>
#include <cuda_fp16.h>
#include <math.h>
#include <stdint.h>

// ---------------- problem constants ----------------
#define L_SEQ 16384
#define D_MOD 512
#define NH 8
#define DH 64
#define FF 2048
#define BATCH 2
#define EPS_F 1e-6f

// GEMM tiling
#define TILE 128
#define KC 64
#define AROW_B 144                      // 128B data + 16B pad
#define HALF_STAGE (128 * AROW_B)       // 18432
#define STAGE_B (2 * HALF_STAGE)        // 36864
#define SMEM_SZ (3 * STAGE_B)           // 110592

// ---------------- scratch (static device globals; no allocation) ----------------
__device__ __align__(128) __half g_h1h[L_SEQ * D_MOD];            // ln1(x[0]) fp16
__device__ __align__(128) __half g_oh [L_SEQ * D_MOD];            // attn out fp16
__device__ __align__(128) __half g_ln2h[BATCH * L_SEQ * D_MOD];   // ln2 fp16
__device__ __align__(128) __half g_th [(size_t)BATCH * L_SEQ * FF]; // gelu(ffn1) fp16
__device__ __align__(128) __half g_Wqh[D_MOD * D_MOD];            // W^T fp16
__device__ __align__(128) __half g_Wkh[D_MOD * D_MOD];
__device__ __align__(128) __half g_Wvh[D_MOD * D_MOD];
__device__ __align__(128) __half g_Woh[D_MOD * D_MOD];
__device__ __align__(128) __half g_W1h[FF * D_MOD];
__device__ __align__(128) __half g_W2h[D_MOD * FF];

__device__ __align__(128) __half g_qh[L_SEQ * D_MOD];             // q,k,v fp16
__device__ __align__(128) __half g_kh[L_SEQ * D_MOD];
__device__ __align__(128) __half g_vh[L_SEQ * D_MOD];
__device__ __align__(16) float g_sa[L_SEQ * D_MOD];
__device__ __align__(16) float g_x2[BATCH * L_SEQ * D_MOD];

__device__ float g_ksum[D_MOD], g_qsum[D_MOD];
__device__ float g_kwsum[D_MOD], g_qwsum[D_MOD];
__device__ float g_sink_in[NH * L_SEQ];
__device__ float g_src_out[NH * L_SEQ];
__device__ float g_alloc[NH * L_SEQ];
__device__ float g_cs[NH * L_SEQ];
__device__ float g_hmax[NH], g_hsum[NH];
__device__ float g_kv[NH * DH * DH];

// ---------------- PTX helpers (baseline sm_80+ only) ----------------
__device__ __forceinline__ uint32_t sm_u32(const void* p) {
    uint32_t a;
    asm("{ .reg .u64 t; cvta.to.shared.u64 t, %1; cvt.u32.u64 %0, t; }" : "=r"(a) : "l"(p));
    return a;
}
__device__ __forceinline__ void cp16(uint32_t s, const void* g) {
    asm volatile("cp.async.cg.shared.global [%0], [%1], 16;" :: "r"(s), "l"(g));
}
__device__ __forceinline__ void cp_commit() {
    asm volatile("cp.async.commit_group;" ::: "memory");
}
__device__ __forceinline__ void ldsm4(uint32_t* r, uint32_t addr) {
    asm volatile("ldmatrix.sync.aligned.m8n8.x4.shared.b16 {%0,%1,%2,%3}, [%4];"
                 : "=r"(r[0]), "=r"(r[1]), "=r"(r[2]), "=r"(r[3]) : "r"(addr));
}
__device__ __forceinline__ void mma16816(float* d, const uint32_t* a, const uint32_t* b) {
    asm volatile(
        "mma.sync.aligned.m16n8k16.row.col.f32.f16.f16.f32 "
        "{%0,%1,%2,%3}, {%4,%5,%6,%7}, {%8,%9}, {%0,%1,%2,%3};"
        : "+f"(d[0]), "+f"(d[1]), "+f"(d[2]), "+f"(d[3])
        : "r"(a[0]), "r"(a[1]), "r"(a[2]), "r"(a[3]), "r"(b[0]), "r"(b[1]));
}

// ---------------- zero accumulators ----------------
__global__ void zero_acc_kernel() {
    int t = blockIdx.x * blockDim.x + threadIdx.x;
    if (t < D_MOD) { g_ksum[t] = 0.f; g_qsum[t] = 0.f; g_kwsum[t] = 0.f; g_qwsum[t] = 0.f; }
    if (t < NH * DH * DH) g_kv[t] = 0.f;
}

// ---------------- weight transpose+cast: W[K,N] -> Wt[N,K] fp16 ----------------
__global__ void wsplit_kernel(const float* __restrict__ W, __half* __restrict__ Wt,
                              int K, int N) {
    __shared__ float tile[32][33];
    int k0 = blockIdx.y * 32, n0 = blockIdx.x * 32;
    int tx = threadIdx.x, ty = threadIdx.y;  // 32 x 8
    for (int i = ty; i < 32; i += 8) tile[i][tx] = W[(size_t)(k0 + i) * N + n0 + tx];
    __syncthreads();
    for (int i = ty; i < 32; i += 8)
        Wt[(size_t)(n0 + i) * K + k0 + tx] = __float2half_rn(tile[tx][i]);
}

// ---------------- layernorm on x[0] -> fp16 h1 ----------------
__global__ void ln1_kernel(const float* __restrict__ x,
                           const float* __restrict__ g,
                           const float* __restrict__ be) {
    __shared__ float sh1[4], sh2[4];
    int row = blockIdx.x;
    int t = threadIdx.x;  // 128
    const float* xr = x + (size_t)row * D_MOD;
    float v0 = xr[t], v1 = xr[t + 128], v2 = xr[t + 256], v3 = xr[t + 384];
    float s = v0 + v1 + v2 + v3;
    float s2 = v0 * v0 + v1 * v1 + v2 * v2 + v3 * v3;
    #pragma unroll
    for (int o = 16; o > 0; o >>= 1) {
        s += __shfl_down_sync(0xffffffffu, s, o);
        s2 += __shfl_down_sync(0xffffffffu, s2, o);
    }
    if ((t & 31) == 0) { sh1[t >> 5] = s; sh2[t >> 5] = s2; }
    __syncthreads();
    s = sh1[0] + sh1[1] + sh1[2] + sh1[3];
    s2 = sh2[0] + sh2[1] + sh2[2] + sh2[3];
    float m = s * (1.f / D_MOD);
    float rstd = rsqrtf(s2 * (1.f / D_MOD) - m * m + 1e-5f);
    __half* op = g_h1h + (size_t)row * D_MOD;
    op[t]       = __float2half_rn((v0 - m) * rstd * g[t]       + be[t]);
    op[t + 128] = __float2half_rn((v1 - m) * rstd * g[t + 128] + be[t + 128]);
    op[t + 256] = __float2half_rn((v2 - m) * rstd * g[t + 256] + be[t + 256]);
    op[t + 384] = __float2half_rn((v3 - m) * rstd * g[t + 384] + be[t + 384]);
}

// ---------------- x2 = x + sa(broadcast); ln2 -> fp16 ----------------
__global__ void addln2_kernel(const float* __restrict__ x,
                              const float* __restrict__ g,
                              const float* __restrict__ be) {
    __shared__ float sh1[4], sh2[4];
    int row = blockIdx.x;
    int l = row & (L_SEQ - 1);
    int t = threadIdx.x;  // 128
    const float* xr = x + (size_t)row * D_MOD;
    const float* sr = g_sa + (size_t)l * D_MOD;
    float v0 = xr[t] + sr[t];
    float v1 = xr[t + 128] + sr[t + 128];
    float v2 = xr[t + 256] + sr[t + 256];
    float v3 = xr[t + 384] + sr[t + 384];
    float* x2p = g_x2 + (size_t)row * D_MOD;
    x2p[t] = v0; x2p[t + 128] = v1; x2p[t + 256] = v2; x2p[t + 384] = v3;
    float s = v0 + v1 + v2 + v3;
    float s2 = v0 * v0 + v1 * v1 + v2 * v2 + v3 * v3;
    #pragma unroll
    for (int o = 16; o > 0; o >>= 1) {
        s += __shfl_down_sync(0xffffffffu, s, o);
        s2 += __shfl_down_sync(0xffffffffu, s2, o);
    }
    if ((t & 31) == 0) { sh1[t >> 5] = s; sh2[t >> 5] = s2; }
    __syncthreads();
    s = sh1[0] + sh1[1] + sh1[2] + sh1[3];
    s2 = sh2[0] + sh2[1] + sh2[2] + sh2[3];
    float m = s * (1.f / D_MOD);
    float rstd = rsqrtf(s2 * (1.f / D_MOD) - m * m + 1e-5f);
    __half* op = g_ln2h + (size_t)row * D_MOD;
    op[t]       = __float2half_rn((v0 - m) * rstd * g[t]       + be[t]);
    op[t + 128] = __float2half_rn((v1 - m) * rstd * g[t + 128] + be[t + 128]);
    op[t + 256] = __float2half_rn((v2 - m) * rstd * g[t + 256] + be[t + 256]);
    op[t + 384] = __float2half_rn((v3 - m) * rstd * g[t + 384] + be[t + 384]);
}

// ---------------- column sums of q, k (fp16 in, fp32 acc) ----------------
__global__ void colsum_qk_kernel() {
    int c = threadIdx.x;
    int r0 = blockIdx.x * 256;
    float sq = 0.f, sk = 0.f;
    for (int r = r0; r < r0 + 256; r++) {
        sq += __half2float(g_qh[(size_t)r * D_MOD + c]);
        sk += __half2float(g_kh[(size_t)r * D_MOD + c]);
    }
    atomicAdd(&g_qsum[c], sq);
    atomicAdd(&g_ksum[c], sk);
}

__global__ void colsum_w_kernel() {
    int c = threadIdx.x;
    int h = c >> 6;
    int r0 = blockIdx.x * 256;
    float sq = 0.f, sk = 0.f;
    for (int r = r0; r < r0 + 256; r++) {
        float si = g_sink_in[h * L_SEQ + r];
        float so = g_src_out[h * L_SEQ + r];
        sq += __half2float(g_qh[(size_t)r * D_MOD + c]) * si;
        sk += __half2float(g_kh[(size_t)r * D_MOD + c]) * so;
    }
    atomicAdd(&g_qwsum[c], sq);
    atomicAdd(&g_kwsum[c], sk);
}

__global__ void stage1_kernel() {
    int w = (blockIdx.x * blockDim.x + threadIdx.x) >> 5;
    int lane = threadIdx.x & 31;
    int h = w >> 14;
    int l = w & (L_SEQ - 1);
    const __half* qr = g_qh + (size_t)l * D_MOD + h * DH;
    const __half* kr = g_kh + (size_t)l * D_MOD + h * DH;
    const float* ks = g_ksum + h * DH;
    const float* qs = g_qsum + h * DH;
    float a = (__half2float(qr[lane]) + EPS_F) * (ks[lane] + EPS_F)
            + (__half2float(qr[lane + 32]) + EPS_F) * (ks[lane + 32] + EPS_F);
    float b = (__half2float(kr[lane]) + EPS_F) * (qs[lane] + EPS_F)
            + (__half2float(kr[lane + 32]) + EPS_F) * (qs[lane + 32] + EPS_F);
    #pragma unroll
    for (int o = 16; o > 0; o >>= 1) {
        a += __shfl_down_sync(0xffffffffu, a, o);
        b += __shfl_down_sync(0xffffffffu, b, o);
    }
    if (lane == 0) {
        g_sink_in[h * L_SEQ + l] = 1.f / a;
        g_src_out[h * L_SEQ + l] = 1.f / b;
    }
}

__global__ void stage2_kernel() {
    int w = (blockIdx.x * blockDim.x + threadIdx.x) >> 5;
    int lane = threadIdx.x & 31;
    int h = w >> 14;
    int l = w & (L_SEQ - 1);
    const __half* qr = g_qh + (size_t)l * D_MOD + h * DH;
    const __half* kr = g_kh + (size_t)l * D_MOD + h * DH;
    const float* kw = g_kwsum + h * DH;
    const float* qw = g_qwsum + h * DH;
    float a = (__half2float(qr[lane]) + EPS_F) * (kw[lane] + EPS_F)
            + (__half2float(qr[lane + 32]) + EPS_F) * (kw[lane + 32] + EPS_F);
    float b = (__half2float(kr[lane]) + EPS_F) * (qw[lane] + EPS_F)
            + (__half2float(kr[lane + 32]) + EPS_F) * (qw[lane + 32] + EPS_F);
    #pragma unroll
    for (int o = 16; o > 0; o >>= 1) {
        a += __shfl_down_sync(0xffffffffu, a, o);
        b += __shfl_down_sync(0xffffffffu, b, o);
    }
    if (lane == 0) {
        g_alloc[h * L_SEQ + l] = 1.f / (1.f + expf(-a));
        g_cs[h * L_SEQ + l] = fminf(fmaxf(b, -1.f), 1.f);
    }
}

__global__ void softmax_head_kernel() {
    __shared__ float sh[32];
    int h = blockIdx.x;
    int t = threadIdx.x;  // 1024
    const float* cs = g_cs + h * L_SEQ;
    float mx = -1e30f;
    for (int i = t; i < L_SEQ; i += 1024) mx = fmaxf(mx, cs[i]);
    #pragma unroll
    for (int o = 16; o > 0; o >>= 1) mx = fmaxf(mx, __shfl_xor_sync(0xffffffffu, mx, o));
    if ((t & 31) == 0) sh[t >> 5] = mx;
    __syncthreads();
    float bm = sh[0];
    #pragma unroll
    for (int i = 1; i < 32; i++) bm = fmaxf(bm, sh[i]);
    __syncthreads();
    float se = 0.f;
    for (int i = t; i < L_SEQ; i += 1024) se += expf(cs[i] - bm);
    #pragma unroll
    for (int o = 16; o > 0; o >>= 1) se += __shfl_xor_sync(0xffffffffu, se, o);
    if ((t & 31) == 0) sh[t >> 5] = se;
    __syncthreads();
    if (t == 0) {
        float s = 0.f;
        #pragma unroll
        for (int i = 0; i < 32; i++) s += sh[i];
        g_hmax[h] = bm;
        g_hsum[h] = s;
    }
}

__global__ void kv_kernel() {
    __shared__ float sk[8][64];
    __shared__ float sv[8][64];
    int h = blockIdx.y;
    int chunk = blockIdx.x;
    int t = threadIdx.x;
    int drow = t >> 2;
    int mbase = (t & 3) << 4;
    float hmax = g_hmax[h];
    float hscale = (float)L_SEQ / g_hsum[h];
    int l0 = chunk * 512;
    float acc[16];
    #pragma unroll
    for (int j = 0; j < 16; j++) acc[j] = 0.f;
    for (int it = 0; it < 64; it++) {
        int lb = l0 + it * 8;
        #pragma unroll
        for (int j = 0; j < 4; j++) {
            int e = t + j * 256;
            if (e < 512) {
                int r = e >> 6, dd = e & 63;
                sk[r][dd] = __half2float(g_kh[(size_t)(lb + r) * D_MOD + h * DH + dd]);
            } else {
                int e2 = e - 512;
                int r = e2 >> 6, dd = e2 & 63;
                int l = lb + r;
                float comp = expf(g_cs[h * L_SEQ + l] - hmax) * hscale;
                sv[r][dd] = __half2float(g_vh[(size_t)l * D_MOD + h * DH + dd]) * comp;
            }
        }
        __syncthreads();
        #pragma unroll
        for (int r = 0; r < 8; r++) {
            float kd = sk[r][drow];
            #pragma unroll
            for (int j = 0; j < 16; j++) acc[j] += kd * sv[r][mbase + j];
        }
        __syncthreads();
    }
    float* kvp = g_kv + h * DH * DH + drow * DH + mbase;
    #pragma unroll
    for (int j = 0; j < 16; j++) atomicAdd(&kvp[j], acc[j]);
}

// ---------------- o = (q*sink_in) @ kv * alloc -> fp16 ----------------
__global__ void o_kernel() {
    __shared__ float kvs[DH * DH];
    __shared__ float qs[32][64];
    int h = blockIdx.y;
    int chunk = blockIdx.x;
    int t = threadIdx.x;
    for (int e = t; e < DH * DH; e += 256) kvs[e] = g_kv[h * DH * DH + e];
    for (int e = t; e < 32 * 64; e += 256) {
        int r = e >> 6, dd = e & 63;
        int l = chunk * 32 + r;
        qs[r][dd] = __half2float(g_qh[(size_t)l * D_MOD + h * DH + dd]) * g_sink_in[h * L_SEQ + l];
    }
    __syncthreads();
    int r = t >> 3;
    int cg = (t & 7) * 8;
    float acc[8];
    #pragma unroll
    for (int j = 0; j < 8; j++) acc[j] = 0.f;
    #pragma unroll
    for (int dd = 0; dd < 64; dd++) {
        float qv = qs[r][dd];
        #pragma unroll
        for (int j = 0; j < 8; j++) acc[j] += qv * kvs[dd * 64 + cg + j];
    }
    int l = chunk * 32 + r;
    float al = g_alloc[h * L_SEQ + l];
    __half* op = g_oh + (size_t)l * D_MOD + h * DH + cg;
    #pragma unroll
    for (int j = 0; j < 8; j++) op[j] = __float2half_rn(acc[j] * al);
}

// ---------------- mma.sync fp16 GEMM ----------------
// A: [M,K] fp16 row-major, B: [N,K] fp16 (W^T). KC=64, 3 stages, 1 sync/iter.
// MODE 0: +bias | 1: sigmoid | 2: gelu | 3: +bias+res.  OUTH: 1 -> half out Ch, 0 -> float Cf.
template <int MODE, int OUTH>
__global__ void __launch_bounds__(256, 2) mm_kernel(
    const __half* __restrict__ A, const __half* __restrict__ B,
    const float* __restrict__ bias, const float* __restrict__ res,
    float* __restrict__ Cf, __half* __restrict__ Ch,
    int N, int K, int nIter) {
    extern __shared__ __align__(128) char smem[];
    uint32_t sb = sm_u32(smem);
    const int tid = threadIdx.x;
    const int wid = tid >> 5, lane = tid & 31;
    const int rowA0 = blockIdx.y * TILE, colB0 = blockIdx.x * TILE;
    const int wm = (wid >> 2) * 64, wn = (wid & 3) * 32;

    const int lrow = tid >> 1;            // 0..127
    const int lcolB = (tid & 1) * 64;     // byte offset in 128B row

    float acc[4][4][4];
    #pragma unroll
    for (int i = 0; i < 4; i++)
        #pragma unroll
        for (int j = 0; j < 4; j++)
            #pragma unroll
            for (int e = 0; e < 4; e++) acc[i][j][e] = 0.f;

    auto load_stage = [&](int slot, int it) {
        const __half* Ag = A + (size_t)(rowA0 + lrow) * K + it * KC + (lcolB >> 1);
        const __half* Bg = B + (size_t)(colB0 + lrow) * K + it * KC + (lcolB >> 1);
        uint32_t sA = sb + slot * STAGE_B + lrow * AROW_B + lcolB;
        uint32_t sB = sA + HALF_STAGE;
        cp16(sA, Ag);       cp16(sA + 16, Ag + 8);
        cp16(sA + 32, Ag + 16); cp16(sA + 48, Ag + 24);
        cp16(sB, Bg);       cp16(sB + 16, Bg + 8);
        cp16(sB + 32, Bg + 16); cp16(sB + 48, Bg + 24);
        cp_commit();
    };

    auto compute_stage = [&](int slot) {
        uint32_t aB = sb + slot * STAGE_B;
        uint32_t bB = aB + HALF_STAGE;
        #pragma unroll
        for (int ks = 0; ks < 4; ks++) {
            uint32_t af[4][4], bfr[2][4];
            #pragma unroll
            for (int mf = 0; mf < 4; mf++)
                ldsm4(af[mf], aB + (uint32_t)((wm + mf * 16 + (lane & 15)) * AROW_B
                                              + ks * 32 + ((lane >> 4) << 4)));
            #pragma unroll
            for (int g = 0; g < 2; g++)
                ldsm4(bfr[g], bB + (uint32_t)((wn + g * 16 + (lane & 7) + ((lane & 16) >> 1)) * AROW_B
                                              + ks * 32 + ((lane & 8) << 1)));
            #pragma unroll
            for (int mf = 0; mf < 4; mf++)
                #pragma unroll
                for (int nf = 0; nf < 4; nf++)
                    mma16816(acc[mf][nf], af[mf], &bfr[nf >> 1][(nf & 1) * 2]);
        }
    };

    load_stage(0, 0);
    load_stage(1, 1);

    int slot = 0, nslot = 2;
    for (int it = 0; it < nIter; it++) {
        asm volatile("cp.async.wait_group 1;" ::: "memory");
        __syncthreads();
        if (it + 2 < nIter) load_stage(nslot, it + 2); else cp_commit();
        compute_stage(slot);
        slot = (slot == 2) ? 0 : slot + 1;
        nslot = (nslot == 2) ? 0 : nslot + 1;
    }

    // ---- epilogue ----
    const int lm = lane >> 2;
    const int ln = (lane & 3) * 2;
    #pragma unroll
    for (int mf = 0; mf < 4; mf++) {
        #pragma unroll
        for (int nf = 0; nf < 4; nf++) {
            int m0 = rowA0 + wm + mf * 16 + lm;
            int n0 = colB0 + wn + nf * 8 + ln;
            float b0 = __ldg(&bias[n0]), b1 = __ldg(&bias[n0 + 1]);
            float f0 = acc[mf][nf][0] + b0;
            float f1 = acc[mf][nf][1] + b1;
            float f2 = acc[mf][nf][2] + b0;
            float f3 = acc[mf][nf][3] + b1;
            if (MODE == 1) {
                f0 = 1.f / (1.f + expf(-f0)); f1 = 1.f / (1.f + expf(-f1));
                f2 = 1.f / (1.f + expf(-f2)); f3 = 1.f / (1.f + expf(-f3));
            } else if (MODE == 2) {
                f0 = 0.5f * f0 * (1.f + erff(f0 * 0.70710678118654752f));
                f1 = 0.5f * f1 * (1.f + erff(f1 * 0.70710678118654752f));
                f2 = 0.5f * f2 * (1.f + erff(f2 * 0.70710678118654752f));
                f3 = 0.5f * f3 * (1.f + erff(f3 * 0.70710678118654752f));
            } else if (MODE == 3) {
                float2 r0 = *(const float2*)(res + (size_t)m0 * N + n0);
                float2 r1 = *(const float2*)(res + (size_t)(m0 + 8) * N + n0);
                f0 += r0.x; f1 += r0.y; f2 += r1.x; f3 += r1.y;
            }
            if (OUTH) {
                __half2 h0; h0.x = __float2half_rn(f0); h0.y = __float2half_rn(f1);
                __half2 h1; h1.x = __float2half_rn(f2); h1.y = __float2half_rn(f3);
                *(__half2*)(Ch + (size_t)m0 * N + n0) = h0;
                *(__half2*)(Ch + (size_t)(m0 + 8) * N + n0) = h1;
            } else {
                float2 v0; v0.x = f0; v0.y = f1;
                float2 v1; v1.x = f2; v1.y = f3;
                *(float2*)(Cf + (size_t)m0 * N + n0) = v0;
                *(float2*)(Cf + (size_t)(m0 + 8) * N + n0) = v1;
            }
        }
    }
}

// ---------------- launcher ----------------
extern "C" void kernel_launch(void* const* d_in, const int* in_sizes, int n_in,
                              void* d_out, int out_size) {
    (void)in_sizes; (void)n_in; (void)out_size;
    const float* x   = (const float*)d_in[0];
    const float* Wq  = (const float*)d_in[1];
    const float* bq  = (const float*)d_in[2];
    const float* Wk  = (const float*)d_in[3];
    const float* bk  = (const float*)d_in[4];
    const float* Wv  = (const float*)d_in[5];
    const float* bv  = (const float*)d_in[6];
    const float* Wo  = (const float*)d_in[7];
    const float* bo  = (const float*)d_in[8];
    const float* W1  = (const float*)d_in[9];
    const float* b1  = (const float*)d_in[10];
    const float* W2  = (const float*)d_in[11];
    const float* b2  = (const float*)d_in[12];
    const float* g1  = (const float*)d_in[13];
    const float* be1 = (const float*)d_in[14];
    const float* g2  = (const float*)d_in[15];
    const float* be2 = (const float*)d_in[16];
    float* out = (float*)d_out;

    __half *p_h1h, *p_oh, *p_ln2h, *p_th, *p_Wqh, *p_Wkh, *p_Wvh, *p_Woh, *p_W1h, *p_W2h;
    __half *p_qh, *p_kh, *p_vh;
    float *p_sa, *p_x2;
    cudaGetSymbolAddress((void**)&p_h1h, g_h1h);
    cudaGetSymbolAddress((void**)&p_oh, g_oh);
    cudaGetSymbolAddress((void**)&p_ln2h, g_ln2h);
    cudaGetSymbolAddress((void**)&p_th, g_th);
    cudaGetSymbolAddress((void**)&p_Wqh, g_Wqh);
    cudaGetSymbolAddress((void**)&p_Wkh, g_Wkh);
    cudaGetSymbolAddress((void**)&p_Wvh, g_Wvh);
    cudaGetSymbolAddress((void**)&p_Woh, g_Woh);
    cudaGetSymbolAddress((void**)&p_W1h, g_W1h);
    cudaGetSymbolAddress((void**)&p_W2h, g_W2h);
    cudaGetSymbolAddress((void**)&p_qh, g_qh);
    cudaGetSymbolAddress((void**)&p_kh, g_kh);
    cudaGetSymbolAddress((void**)&p_vh, g_vh);
    cudaGetSymbolAddress((void**)&p_sa, g_sa);
    cudaGetSymbolAddress((void**)&p_x2, g_x2);

    cudaFuncSetAttribute(mm_kernel<0,0>, cudaFuncAttributeMaxDynamicSharedMemorySize, SMEM_SZ);
    cudaFuncSetAttribute(mm_kernel<0,1>, cudaFuncAttributeMaxDynamicSharedMemorySize, SMEM_SZ);
    cudaFuncSetAttribute(mm_kernel<1,1>, cudaFuncAttributeMaxDynamicSharedMemorySize, SMEM_SZ);
    cudaFuncSetAttribute(mm_kernel<2,1>, cudaFuncAttributeMaxDynamicSharedMemorySize, SMEM_SZ);
    cudaFuncSetAttribute(mm_kernel<3,0>, cudaFuncAttributeMaxDynamicSharedMemorySize, SMEM_SZ);

    zero_acc_kernel<<<128, 256>>>();

    dim3 wblk(32, 8);
    wsplit_kernel<<<dim3(D_MOD / 32, D_MOD / 32), wblk>>>(Wq, p_Wqh, D_MOD, D_MOD);
    wsplit_kernel<<<dim3(D_MOD / 32, D_MOD / 32), wblk>>>(Wk, p_Wkh, D_MOD, D_MOD);
    wsplit_kernel<<<dim3(D_MOD / 32, D_MOD / 32), wblk>>>(Wv, p_Wvh, D_MOD, D_MOD);
    wsplit_kernel<<<dim3(D_MOD / 32, D_MOD / 32), wblk>>>(Wo, p_Woh, D_MOD, D_MOD);
    wsplit_kernel<<<dim3(FF / 32, D_MOD / 32), wblk>>>(W1, p_W1h, D_MOD, FF);
    wsplit_kernel<<<dim3(D_MOD / 32, FF / 32), wblk>>>(W2, p_W2h, FF, D_MOD);

    ln1_kernel<<<L_SEQ, 128>>>(x, g1, be1);

    // K=512: nIter = 8
    dim3 gqkv(D_MOD / TILE, L_SEQ / TILE);  // (4, 128)
    mm_kernel<1,1><<<gqkv, 256, SMEM_SZ>>>(p_h1h, p_Wqh, bq, nullptr, nullptr, p_qh, D_MOD, D_MOD, 8);
    mm_kernel<1,1><<<gqkv, 256, SMEM_SZ>>>(p_h1h, p_Wkh, bk, nullptr, nullptr, p_kh, D_MOD, D_MOD, 8);
    mm_kernel<0,1><<<gqkv, 256, SMEM_SZ>>>(p_h1h, p_Wvh, bv, nullptr, nullptr, p_vh, D_MOD, D_MOD, 8);

    colsum_qk_kernel<<<64, 512>>>();
    stage1_kernel<<<(NH * L_SEQ) / 8, 256>>>();
    colsum_w_kernel<<<64, 512>>>();
    stage2_kernel<<<(NH * L_SEQ) / 8, 256>>>();
    softmax_head_kernel<<<NH, 1024>>>();
    kv_kernel<<<dim3(32, NH), 256>>>();
    o_kernel<<<dim3(L_SEQ / 32, NH), 256>>>();

    mm_kernel<0,0><<<gqkv, 256, SMEM_SZ>>>(p_oh, p_Woh, bo, nullptr, p_sa, nullptr, D_MOD, D_MOD, 8);

    addln2_kernel<<<BATCH * L_SEQ, 128>>>(x, g2, be2);

    dim3 gf1(FF / TILE, (BATCH * L_SEQ) / TILE);    // (16, 256)
    mm_kernel<2,1><<<gf1, 256, SMEM_SZ>>>(p_ln2h, p_W1h, b1, nullptr, nullptr, p_th, FF, D_MOD, 8);

    // K=2048: nIter = 32
    dim3 gf2(D_MOD / TILE, (BATCH * L_SEQ) / TILE); // (4, 256)
    mm_kernel<3,0><<<gf2, 256, SMEM_SZ>>>(p_th, p_W2h, b2, p_x2, out, nullptr, D_MOD, FF, 32);
}

// round 6
// speedup vs baseline: 3.6262x; 1.0262x over previous
#include <cuda_runtime.h>
#include <cuda_fp16.h>
#include <math.h>
#include <stdint.h>

// ---------------- problem constants ----------------
#define L_SEQ 16384
#define D_MOD 512
#define NH 8
#define DH 64
#define FF 2048
#define BATCH 2
#define EPS_F 1e-6f

// GEMM tiling
#define TILE 128
#define KC 64
#define AROW_B 144                      // 128B data + 16B pad
#define HALF_STAGE (128 * AROW_B)       // 18432
#define STAGE_B (2 * HALF_STAGE)        // 36864
#define SMEM_SZ (3 * STAGE_B)           // 110592

// ---------------- scratch (static device globals; no allocation) ----------------
__device__ __align__(128) __half g_h1h[L_SEQ * D_MOD];            // ln1(x[0]) fp16
__device__ __align__(128) __half g_oh [L_SEQ * D_MOD];            // attn out fp16
__device__ __align__(128) __half g_ln2h[BATCH * L_SEQ * D_MOD];   // ln2 fp16
__device__ __align__(128) __half g_th [(size_t)BATCH * L_SEQ * FF]; // gelu(ffn1) fp16
__device__ __align__(128) __half g_Wqh[D_MOD * D_MOD];            // W^T fp16
__device__ __align__(128) __half g_Wkh[D_MOD * D_MOD];
__device__ __align__(128) __half g_Wvh[D_MOD * D_MOD];
__device__ __align__(128) __half g_Woh[D_MOD * D_MOD];
__device__ __align__(128) __half g_W1h[FF * D_MOD];
__device__ __align__(128) __half g_W2h[D_MOD * FF];

__device__ __align__(128) __half g_qh[L_SEQ * D_MOD];             // q,k,v fp16
__device__ __align__(128) __half g_kh[L_SEQ * D_MOD];
__device__ __align__(128) __half g_vh[L_SEQ * D_MOD];
__device__ __align__(16) float g_sa[L_SEQ * D_MOD];

__device__ float g_ksum[D_MOD], g_qsum[D_MOD];
__device__ float g_kwsum[D_MOD], g_qwsum[D_MOD];
__device__ float g_sink_in[NH * L_SEQ];
__device__ float g_src_out[NH * L_SEQ];
__device__ float g_alloc[NH * L_SEQ];
__device__ float g_cs[NH * L_SEQ];
__device__ float g_hmax[NH], g_hsum[NH];
__device__ float g_kv[NH * DH * DH];

// ---------------- PTX helpers (baseline sm_80+ only) ----------------
__device__ __forceinline__ uint32_t sm_u32(const void* p) {
    uint32_t a;
    asm("{ .reg .u64 t; cvta.to.shared.u64 t, %1; cvt.u32.u64 %0, t; }" : "=r"(a) : "l"(p));
    return a;
}
__device__ __forceinline__ void cp16(uint32_t s, const void* g) {
    asm volatile("cp.async.cg.shared.global [%0], [%1], 16;" :: "r"(s), "l"(g));
}
__device__ __forceinline__ void cp_commit() {
    asm volatile("cp.async.commit_group;" ::: "memory");
}
__device__ __forceinline__ void ldsm4(uint32_t* r, uint32_t addr) {
    asm volatile("ldmatrix.sync.aligned.m8n8.x4.shared.b16 {%0,%1,%2,%3}, [%4];"
                 : "=r"(r[0]), "=r"(r[1]), "=r"(r[2]), "=r"(r[3]) : "r"(addr));
}
__device__ __forceinline__ void mma16816(float* d, const uint32_t* a, const uint32_t* b) {
    asm volatile(
        "mma.sync.aligned.m16n8k16.row.col.f32.f16.f16.f32 "
        "{%0,%1,%2,%3}, {%4,%5,%6,%7}, {%8,%9}, {%0,%1,%2,%3};"
        : "+f"(d[0]), "+f"(d[1]), "+f"(d[2]), "+f"(d[3])
        : "r"(a[0]), "r"(a[1]), "r"(a[2]), "r"(a[3]), "r"(b[0]), "r"(b[1]));
}

// ---------------- fused prep: zero accumulators + all weight transposes ----------------
// Block ranges: [0,256) Wq | [256,512) Wk | [512,768) Wv | [768,1024) Wo
//               [1024,2048) W1 (K=512,N=2048) | [2048,3072) W2 (K=2048,N=512) | 3072 zero
__global__ void prep_kernel(const float* __restrict__ Wq, const float* __restrict__ Wk,
                            const float* __restrict__ Wv, const float* __restrict__ Wo,
                            const float* __restrict__ W1, const float* __restrict__ W2,
                            __half* __restrict__ Wqh, __half* __restrict__ Wkh,
                            __half* __restrict__ Wvh, __half* __restrict__ Woh,
                            __half* __restrict__ W1h, __half* __restrict__ W2h) {
    int b = blockIdx.x;
    if (b == 3072) {
        int t = threadIdx.y * 32 + threadIdx.x;  // 256
        for (int i = t; i < 4 * D_MOD; i += 256) {
            if (i < D_MOD) g_ksum[i] = 0.f;
            else if (i < 2 * D_MOD) g_qsum[i - D_MOD] = 0.f;
            else if (i < 3 * D_MOD) g_kwsum[i - 2 * D_MOD] = 0.f;
            else g_qwsum[i - 3 * D_MOD] = 0.f;
        }
        for (int i = t; i < NH * DH * DH; i += 256) g_kv[i] = 0.f;
        return;
    }
    const float* W; __half* Wt; int K, N, tix;
    if (b < 1024) {
        K = D_MOD; N = D_MOD;
        int w = b >> 8; tix = b & 255;
        W = (w == 0) ? Wq : (w == 1) ? Wk : (w == 2) ? Wv : Wo;
        Wt = (w == 0) ? Wqh : (w == 1) ? Wkh : (w == 2) ? Wvh : Woh;
    } else if (b < 2048) {
        K = D_MOD; N = FF; tix = b - 1024; W = W1; Wt = W1h;
    } else {
        K = FF; N = D_MOD; tix = b - 2048; W = W2; Wt = W2h;
    }
    int ntx = N / 32;
    int bx = tix % ntx, by = tix / ntx;
    __shared__ float tile[32][33];
    int k0 = by * 32, n0 = bx * 32;
    int tx = threadIdx.x, ty = threadIdx.y;  // 32 x 8
    for (int i = ty; i < 32; i += 8) tile[i][tx] = W[(size_t)(k0 + i) * N + n0 + tx];
    __syncthreads();
    for (int i = ty; i < 32; i += 8)
        Wt[(size_t)(n0 + i) * K + k0 + tx] = __float2half_rn(tile[tx][i]);
}

// ---------------- layernorm on x[0] -> fp16 h1 ----------------
__global__ void ln1_kernel(const float* __restrict__ x,
                           const float* __restrict__ g,
                           const float* __restrict__ be) {
    __shared__ float sh1[4], sh2[4];
    int row = blockIdx.x;
    int t = threadIdx.x;  // 128
    const float* xr = x + (size_t)row * D_MOD;
    float v0 = xr[t], v1 = xr[t + 128], v2 = xr[t + 256], v3 = xr[t + 384];
    float s = v0 + v1 + v2 + v3;
    float s2 = v0 * v0 + v1 * v1 + v2 * v2 + v3 * v3;
    #pragma unroll
    for (int o = 16; o > 0; o >>= 1) {
        s += __shfl_down_sync(0xffffffffu, s, o);
        s2 += __shfl_down_sync(0xffffffffu, s2, o);
    }
    if ((t & 31) == 0) { sh1[t >> 5] = s; sh2[t >> 5] = s2; }
    __syncthreads();
    s = sh1[0] + sh1[1] + sh1[2] + sh1[3];
    s2 = sh2[0] + sh2[1] + sh2[2] + sh2[3];
    float m = s * (1.f / D_MOD);
    float rstd = rsqrtf(s2 * (1.f / D_MOD) - m * m + 1e-5f);
    __half* op = g_h1h + (size_t)row * D_MOD;
    op[t]       = __float2half_rn((v0 - m) * rstd * g[t]       + be[t]);
    op[t + 128] = __float2half_rn((v1 - m) * rstd * g[t + 128] + be[t + 128]);
    op[t + 256] = __float2half_rn((v2 - m) * rstd * g[t + 256] + be[t + 256]);
    op[t + 384] = __float2half_rn((v3 - m) * rstd * g[t + 384] + be[t + 384]);
}

// ---------------- x+sa; ln2 -> fp16 (no x2 materialization) ----------------
__global__ void addln2_kernel(const float* __restrict__ x,
                              const float* __restrict__ g,
                              const float* __restrict__ be) {
    __shared__ float sh1[4], sh2[4];
    int row = blockIdx.x;
    int l = row & (L_SEQ - 1);
    int t = threadIdx.x;  // 128
    const float* xr = x + (size_t)row * D_MOD;
    const float* sr = g_sa + (size_t)l * D_MOD;
    float v0 = xr[t] + sr[t];
    float v1 = xr[t + 128] + sr[t + 128];
    float v2 = xr[t + 256] + sr[t + 256];
    float v3 = xr[t + 384] + sr[t + 384];
    float s = v0 + v1 + v2 + v3;
    float s2 = v0 * v0 + v1 * v1 + v2 * v2 + v3 * v3;
    #pragma unroll
    for (int o = 16; o > 0; o >>= 1) {
        s += __shfl_down_sync(0xffffffffu, s, o);
        s2 += __shfl_down_sync(0xffffffffu, s2, o);
    }
    if ((t & 31) == 0) { sh1[t >> 5] = s; sh2[t >> 5] = s2; }
    __syncthreads();
    s = sh1[0] + sh1[1] + sh1[2] + sh1[3];
    s2 = sh2[0] + sh2[1] + sh2[2] + sh2[3];
    float m = s * (1.f / D_MOD);
    float rstd = rsqrtf(s2 * (1.f / D_MOD) - m * m + 1e-5f);
    __half* op = g_ln2h + (size_t)row * D_MOD;
    op[t]       = __float2half_rn((v0 - m) * rstd * g[t]       + be[t]);
    op[t + 128] = __float2half_rn((v1 - m) * rstd * g[t + 128] + be[t + 128]);
    op[t + 256] = __float2half_rn((v2 - m) * rstd * g[t + 256] + be[t + 256]);
    op[t + 384] = __float2half_rn((v3 - m) * rstd * g[t + 384] + be[t + 384]);
}

// ---------------- column sums of q, k (fp16 in, fp32 acc) ----------------
__global__ void colsum_qk_kernel() {
    int c = threadIdx.x;
    int r0 = blockIdx.x * 256;
    float sq = 0.f, sk = 0.f;
    for (int r = r0; r < r0 + 256; r++) {
        sq += __half2float(g_qh[(size_t)r * D_MOD + c]);
        sk += __half2float(g_kh[(size_t)r * D_MOD + c]);
    }
    atomicAdd(&g_qsum[c], sq);
    atomicAdd(&g_ksum[c], sk);
}

__global__ void colsum_w_kernel() {
    int c = threadIdx.x;
    int h = c >> 6;
    int r0 = blockIdx.x * 256;
    float sq = 0.f, sk = 0.f;
    for (int r = r0; r < r0 + 256; r++) {
        float si = g_sink_in[h * L_SEQ + r];
        float so = g_src_out[h * L_SEQ + r];
        sq += __half2float(g_qh[(size_t)r * D_MOD + c]) * si;
        sk += __half2float(g_kh[(size_t)r * D_MOD + c]) * so;
    }
    atomicAdd(&g_qwsum[c], sq);
    atomicAdd(&g_kwsum[c], sk);
}

__global__ void stage1_kernel() {
    int w = (blockIdx.x * blockDim.x + threadIdx.x) >> 5;
    int lane = threadIdx.x & 31;
    int h = w >> 14;
    int l = w & (L_SEQ - 1);
    const __half* qr = g_qh + (size_t)l * D_MOD + h * DH;
    const __half* kr = g_kh + (size_t)l * D_MOD + h * DH;
    const float* ks = g_ksum + h * DH;
    const float* qs = g_qsum + h * DH;
    float a = (__half2float(qr[lane]) + EPS_F) * (ks[lane] + EPS_F)
            + (__half2float(qr[lane + 32]) + EPS_F) * (ks[lane + 32] + EPS_F);
    float b = (__half2float(kr[lane]) + EPS_F) * (qs[lane] + EPS_F)
            + (__half2float(kr[lane + 32]) + EPS_F) * (qs[lane + 32] + EPS_F);
    #pragma unroll
    for (int o = 16; o > 0; o >>= 1) {
        a += __shfl_down_sync(0xffffffffu, a, o);
        b += __shfl_down_sync(0xffffffffu, b, o);
    }
    if (lane == 0) {
        g_sink_in[h * L_SEQ + l] = 1.f / a;
        g_src_out[h * L_SEQ + l] = 1.f / b;
    }
}

__global__ void stage2_kernel() {
    int w = (blockIdx.x * blockDim.x + threadIdx.x) >> 5;
    int lane = threadIdx.x & 31;
    int h = w >> 14;
    int l = w & (L_SEQ - 1);
    const __half* qr = g_qh + (size_t)l * D_MOD + h * DH;
    const __half* kr = g_kh + (size_t)l * D_MOD + h * DH;
    const float* kw = g_kwsum + h * DH;
    const float* qw = g_qwsum + h * DH;
    float a = (__half2float(qr[lane]) + EPS_F) * (kw[lane] + EPS_F)
            + (__half2float(qr[lane + 32]) + EPS_F) * (kw[lane + 32] + EPS_F);
    float b = (__half2float(kr[lane]) + EPS_F) * (qw[lane] + EPS_F)
            + (__half2float(kr[lane + 32]) + EPS_F) * (qw[lane + 32] + EPS_F);
    #pragma unroll
    for (int o = 16; o > 0; o >>= 1) {
        a += __shfl_down_sync(0xffffffffu, a, o);
        b += __shfl_down_sync(0xffffffffu, b, o);
    }
    if (lane == 0) {
        g_alloc[h * L_SEQ + l] = 1.f / (1.f + expf(-a));
        g_cs[h * L_SEQ + l] = fminf(fmaxf(b, -1.f), 1.f);
    }
}

__global__ void softmax_head_kernel() {
    __shared__ float sh[32];
    int h = blockIdx.x;
    int t = threadIdx.x;  // 1024
    const float* cs = g_cs + h * L_SEQ;
    float mx = -1e30f;
    for (int i = t; i < L_SEQ; i += 1024) mx = fmaxf(mx, cs[i]);
    #pragma unroll
    for (int o = 16; o > 0; o >>= 1) mx = fmaxf(mx, __shfl_xor_sync(0xffffffffu, mx, o));
    if ((t & 31) == 0) sh[t >> 5] = mx;
    __syncthreads();
    float bm = sh[0];
    #pragma unroll
    for (int i = 1; i < 32; i++) bm = fmaxf(bm, sh[i]);
    __syncthreads();
    float se = 0.f;
    for (int i = t; i < L_SEQ; i += 1024) se += expf(cs[i] - bm);
    #pragma unroll
    for (int o = 16; o > 0; o >>= 1) se += __shfl_xor_sync(0xffffffffu, se, o);
    if ((t & 31) == 0) sh[t >> 5] = se;
    __syncthreads();
    if (t == 0) {
        float s = 0.f;
        #pragma unroll
        for (int i = 0; i < 32; i++) s += sh[i];
        g_hmax[h] = bm;
        g_hsum[h] = s;
    }
}

__global__ void kv_kernel() {
    __shared__ float sk[8][64];
    __shared__ float sv[8][64];
    int h = blockIdx.y;
    int chunk = blockIdx.x;
    int t = threadIdx.x;
    int drow = t >> 2;
    int mbase = (t & 3) << 4;
    float hmax = g_hmax[h];
    float hscale = (float)L_SEQ / g_hsum[h];
    int l0 = chunk * 512;
    float acc[16];
    #pragma unroll
    for (int j = 0; j < 16; j++) acc[j] = 0.f;
    for (int it = 0; it < 64; it++) {
        int lb = l0 + it * 8;
        #pragma unroll
        for (int j = 0; j < 4; j++) {
            int e = t + j * 256;
            if (e < 512) {
                int r = e >> 6, dd = e & 63;
                sk[r][dd] = __half2float(g_kh[(size_t)(lb + r) * D_MOD + h * DH + dd]);
            } else {
                int e2 = e - 512;
                int r = e2 >> 6, dd = e2 & 63;
                int l = lb + r;
                float comp = expf(g_cs[h * L_SEQ + l] - hmax) * hscale;
                sv[r][dd] = __half2float(g_vh[(size_t)l * D_MOD + h * DH + dd]) * comp;
            }
        }
        __syncthreads();
        #pragma unroll
        for (int r = 0; r < 8; r++) {
            float kd = sk[r][drow];
            #pragma unroll
            for (int j = 0; j < 16; j++) acc[j] += kd * sv[r][mbase + j];
        }
        __syncthreads();
    }
    float* kvp = g_kv + h * DH * DH + drow * DH + mbase;
    #pragma unroll
    for (int j = 0; j < 16; j++) atomicAdd(&kvp[j], acc[j]);
}

// ---------------- o = (q*sink_in) @ kv * alloc -> fp16 ----------------
__global__ void o_kernel() {
    __shared__ float kvs[DH * DH];
    __shared__ float qs[32][64];
    int h = blockIdx.y;
    int chunk = blockIdx.x;
    int t = threadIdx.x;
    for (int e = t; e < DH * DH; e += 256) kvs[e] = g_kv[h * DH * DH + e];
    for (int e = t; e < 32 * 64; e += 256) {
        int r = e >> 6, dd = e & 63;
        int l = chunk * 32 + r;
        qs[r][dd] = __half2float(g_qh[(size_t)l * D_MOD + h * DH + dd]) * g_sink_in[h * L_SEQ + l];
    }
    __syncthreads();
    int r = t >> 3;
    int cg = (t & 7) * 8;
    float acc[8];
    #pragma unroll
    for (int j = 0; j < 8; j++) acc[j] = 0.f;
    #pragma unroll
    for (int dd = 0; dd < 64; dd++) {
        float qv = qs[r][dd];
        #pragma unroll
        for (int j = 0; j < 8; j++) acc[j] += qv * kvs[dd * 64 + cg + j];
    }
    int l = chunk * 32 + r;
    float al = g_alloc[h * L_SEQ + l];
    __half* op = g_oh + (size_t)l * D_MOD + h * DH + cg;
    #pragma unroll
    for (int j = 0; j < 8; j++) op[j] = __float2half_rn(acc[j] * al);
}

// =====================================================================
// GEMM machinery (identical mainloop to round 5; KC=64, 3 stages)
// =====================================================================
struct MMFrag { float acc[4][4][4]; };

__device__ __forceinline__ void mm_mainloop(
    uint32_t sb, const __half* A, const __half* B, int K, int nIter,
    int rowA0, int colB0, int tid, int wid, int lane, int wm, int wn,
    float (*acc)[4][4]) {
    const int lrow = tid >> 1;
    const int lcolB = (tid & 1) * 64;

    auto load_stage = [&](int slot, int it) {
        const __half* Ag = A + (size_t)(rowA0 + lrow) * K + it * KC + (lcolB >> 1);
        const __half* Bg = B + (size_t)(colB0 + lrow) * K + it * KC + (lcolB >> 1);
        uint32_t sA = sb + slot * STAGE_B + lrow * AROW_B + lcolB;
        uint32_t sB = sA + HALF_STAGE;
        cp16(sA, Ag);       cp16(sA + 16, Ag + 8);
        cp16(sA + 32, Ag + 16); cp16(sA + 48, Ag + 24);
        cp16(sB, Bg);       cp16(sB + 16, Bg + 8);
        cp16(sB + 32, Bg + 16); cp16(sB + 48, Bg + 24);
        cp_commit();
    };

    auto compute_stage = [&](int slot) {
        uint32_t aB = sb + slot * STAGE_B;
        uint32_t bB = aB + HALF_STAGE;
        #pragma unroll
        for (int ks = 0; ks < 4; ks++) {
            uint32_t af[4][4], bfr[2][4];
            #pragma unroll
            for (int mf = 0; mf < 4; mf++)
                ldsm4(af[mf], aB + (uint32_t)((wm + mf * 16 + (lane & 15)) * AROW_B
                                              + ks * 32 + ((lane >> 4) << 4)));
            #pragma unroll
            for (int g = 0; g < 2; g++)
                ldsm4(bfr[g], bB + (uint32_t)((wn + g * 16 + (lane & 7) + ((lane & 16) >> 1)) * AROW_B
                                              + ks * 32 + ((lane & 8) << 1)));
            #pragma unroll
            for (int mf = 0; mf < 4; mf++)
                #pragma unroll
                for (int nf = 0; nf < 4; nf++)
                    mma16816(acc[mf][nf], af[mf], &bfr[nf >> 1][(nf & 1) * 2]);
        }
    };

    load_stage(0, 0);
    load_stage(1, 1);

    int slot = 0, nslot = 2;
    for (int it = 0; it < nIter; it++) {
        asm volatile("cp.async.wait_group 1;" ::: "memory");
        __syncthreads();
        if (it + 2 < nIter) load_stage(nslot, it + 2); else cp_commit();
        compute_stage(slot);
        slot = (slot == 2) ? 0 : slot + 1;
        nslot = (nslot == 2) ? 0 : nslot + 1;
    }
}

// ---------------- fused QKV GEMM: one launch, 3 weights / outputs ----------------
__global__ void __launch_bounds__(256, 2) qkv_kernel(
    const __half* __restrict__ A,
    const __half* __restrict__ Bq, const __half* __restrict__ Bk, const __half* __restrict__ Bv,
    const float* __restrict__ bq, const float* __restrict__ bk, const float* __restrict__ bv,
    __half* __restrict__ Oq, __half* __restrict__ Ok, __half* __restrict__ Ov) {
    extern __shared__ __align__(128) char smem[];
    uint32_t sb = sm_u32(smem);
    const int tid = threadIdx.x;
    const int wid = tid >> 5, lane = tid & 31;
    const int which = blockIdx.x >> 2;
    const int rowA0 = blockIdx.y * TILE, colB0 = (blockIdx.x & 3) * TILE;
    const int wm = (wid >> 2) * 64, wn = (wid & 3) * 32;

    const __half* B = (which == 0) ? Bq : (which == 1) ? Bk : Bv;
    const float* bias = (which == 0) ? bq : (which == 1) ? bk : bv;
    __half* Ch = (which == 0) ? Oq : (which == 1) ? Ok : Ov;
    const bool sig = (which < 2);

    float acc[4][4][4];
    #pragma unroll
    for (int i = 0; i < 4; i++)
        #pragma unroll
        for (int j = 0; j < 4; j++)
            #pragma unroll
            for (int e = 0; e < 4; e++) acc[i][j][e] = 0.f;

    mm_mainloop(sb, A, B, D_MOD, D_MOD / KC, rowA0, colB0, tid, wid, lane, wm, wn, acc);

    const int lm = lane >> 2;
    const int ln = (lane & 3) * 2;
    #pragma unroll
    for (int mf = 0; mf < 4; mf++) {
        #pragma unroll
        for (int nf = 0; nf < 4; nf++) {
            int m0 = rowA0 + wm + mf * 16 + lm;
            int n0 = colB0 + wn + nf * 8 + ln;
            float b0 = __ldg(&bias[n0]), b1 = __ldg(&bias[n0 + 1]);
            float f0 = acc[mf][nf][0] + b0;
            float f1 = acc[mf][nf][1] + b1;
            float f2 = acc[mf][nf][2] + b0;
            float f3 = acc[mf][nf][3] + b1;
            if (sig) {
                f0 = 1.f / (1.f + expf(-f0)); f1 = 1.f / (1.f + expf(-f1));
                f2 = 1.f / (1.f + expf(-f2)); f3 = 1.f / (1.f + expf(-f3));
            }
            __half2 h0; h0.x = __float2half_rn(f0); h0.y = __float2half_rn(f1);
            __half2 h1; h1.x = __float2half_rn(f2); h1.y = __float2half_rn(f3);
            *(__half2*)(Ch + (size_t)m0 * D_MOD + n0) = h0;
            *(__half2*)(Ch + (size_t)(m0 + 8) * D_MOD + n0) = h1;
        }
    }
}

// ---------------- generic GEMM ----------------
// MODE 0: +bias (float or half out) | 2: gelu (half out) | 4: +bias + x[row] + sa[row&mask] (float out)
template <int MODE, int OUTH>
__global__ void __launch_bounds__(256, 2) mm_kernel(
    const __half* __restrict__ A, const __half* __restrict__ B,
    const float* __restrict__ bias, const float* __restrict__ resx,
    float* __restrict__ Cf, __half* __restrict__ Ch,
    int N, int K, int nIter) {
    extern __shared__ __align__(128) char smem[];
    uint32_t sb = sm_u32(smem);
    const int tid = threadIdx.x;
    const int wid = tid >> 5, lane = tid & 31;
    const int rowA0 = blockIdx.y * TILE, colB0 = blockIdx.x * TILE;
    const int wm = (wid >> 2) * 64, wn = (wid & 3) * 32;

    float acc[4][4][4];
    #pragma unroll
    for (int i = 0; i < 4; i++)
        #pragma unroll
        for (int j = 0; j < 4; j++)
            #pragma unroll
            for (int e = 0; e < 4; e++) acc[i][j][e] = 0.f;

    mm_mainloop(sb, A, B, K, nIter, rowA0, colB0, tid, wid, lane, wm, wn, acc);

    const int lm = lane >> 2;
    const int ln = (lane & 3) * 2;
    #pragma unroll
    for (int mf = 0; mf < 4; mf++) {
        #pragma unroll
        for (int nf = 0; nf < 4; nf++) {
            int m0 = rowA0 + wm + mf * 16 + lm;
            int n0 = colB0 + wn + nf * 8 + ln;
            float b0 = __ldg(&bias[n0]), b1 = __ldg(&bias[n0 + 1]);
            float f0 = acc[mf][nf][0] + b0;
            float f1 = acc[mf][nf][1] + b1;
            float f2 = acc[mf][nf][2] + b0;
            float f3 = acc[mf][nf][3] + b1;
            if (MODE == 2) {
                f0 = 0.5f * f0 * (1.f + erff(f0 * 0.70710678118654752f));
                f1 = 0.5f * f1 * (1.f + erff(f1 * 0.70710678118654752f));
                f2 = 0.5f * f2 * (1.f + erff(f2 * 0.70710678118654752f));
                f3 = 0.5f * f3 * (1.f + erff(f3 * 0.70710678118654752f));
            } else if (MODE == 4) {
                int l0r = m0 & (L_SEQ - 1), l1r = (m0 + 8) & (L_SEQ - 1);
                float2 r0 = *(const float2*)(resx + (size_t)m0 * N + n0);
                float2 r1 = *(const float2*)(resx + (size_t)(m0 + 8) * N + n0);
                float2 s0 = *(const float2*)(g_sa + (size_t)l0r * N + n0);
                float2 s1 = *(const float2*)(g_sa + (size_t)l1r * N + n0);
                f0 += r0.x + s0.x; f1 += r0.y + s0.y;
                f2 += r1.x + s1.x; f3 += r1.y + s1.y;
            }
            if (OUTH) {
                __half2 h0; h0.x = __float2half_rn(f0); h0.y = __float2half_rn(f1);
                __half2 h1; h1.x = __float2half_rn(f2); h1.y = __float2half_rn(f3);
                *(__half2*)(Ch + (size_t)m0 * N + n0) = h0;
                *(__half2*)(Ch + (size_t)(m0 + 8) * N + n0) = h1;
            } else {
                float2 v0; v0.x = f0; v0.y = f1;
                float2 v1; v1.x = f2; v1.y = f3;
                *(float2*)(Cf + (size_t)m0 * N + n0) = v0;
                *(float2*)(Cf + (size_t)(m0 + 8) * N + n0) = v1;
            }
        }
    }
}

// ---------------- launcher ----------------
extern "C" void kernel_launch(void* const* d_in, const int* in_sizes, int n_in,
                              void* d_out, int out_size) {
    (void)in_sizes; (void)n_in; (void)out_size;
    const float* x   = (const float*)d_in[0];
    const float* Wq  = (const float*)d_in[1];
    const float* bq  = (const float*)d_in[2];
    const float* Wk  = (const float*)d_in[3];
    const float* bk  = (const float*)d_in[4];
    const float* Wv  = (const float*)d_in[5];
    const float* bv  = (const float*)d_in[6];
    const float* Wo  = (const float*)d_in[7];
    const float* bo  = (const float*)d_in[8];
    const float* W1  = (const float*)d_in[9];
    const float* b1  = (const float*)d_in[10];
    const float* W2  = (const float*)d_in[11];
    const float* b2  = (const float*)d_in[12];
    const float* g1  = (const float*)d_in[13];
    const float* be1 = (const float*)d_in[14];
    const float* g2  = (const float*)d_in[15];
    const float* be2 = (const float*)d_in[16];
    float* out = (float*)d_out;

    __half *p_h1h, *p_oh, *p_ln2h, *p_th, *p_Wqh, *p_Wkh, *p_Wvh, *p_Woh, *p_W1h, *p_W2h;
    __half *p_qh, *p_kh, *p_vh;
    float *p_sa;
    cudaGetSymbolAddress((void**)&p_h1h, g_h1h);
    cudaGetSymbolAddress((void**)&p_oh, g_oh);
    cudaGetSymbolAddress((void**)&p_ln2h, g_ln2h);
    cudaGetSymbolAddress((void**)&p_th, g_th);
    cudaGetSymbolAddress((void**)&p_Wqh, g_Wqh);
    cudaGetSymbolAddress((void**)&p_Wkh, g_Wkh);
    cudaGetSymbolAddress((void**)&p_Wvh, g_Wvh);
    cudaGetSymbolAddress((void**)&p_Woh, g_Woh);
    cudaGetSymbolAddress((void**)&p_W1h, g_W1h);
    cudaGetSymbolAddress((void**)&p_W2h, g_W2h);
    cudaGetSymbolAddress((void**)&p_qh, g_qh);
    cudaGetSymbolAddress((void**)&p_kh, g_kh);
    cudaGetSymbolAddress((void**)&p_vh, g_vh);
    cudaGetSymbolAddress((void**)&p_sa, g_sa);

    cudaFuncSetAttribute(qkv_kernel, cudaFuncAttributeMaxDynamicSharedMemorySize, SMEM_SZ);
    cudaFuncSetAttribute(mm_kernel<0,0>, cudaFuncAttributeMaxDynamicSharedMemorySize, SMEM_SZ);
    cudaFuncSetAttribute(mm_kernel<2,1>, cudaFuncAttributeMaxDynamicSharedMemorySize, SMEM_SZ);
    cudaFuncSetAttribute(mm_kernel<4,0>, cudaFuncAttributeMaxDynamicSharedMemorySize, SMEM_SZ);

    dim3 wblk(32, 8);
    prep_kernel<<<3073, wblk>>>(Wq, Wk, Wv, Wo, W1, W2,
                                p_Wqh, p_Wkh, p_Wvh, p_Woh, p_W1h, p_W2h);
    ln1_kernel<<<L_SEQ, 128>>>(x, g1, be1);

    // fused QKV: grid (12, 128), K=512 -> nIter=8
    dim3 gq(12, L_SEQ / TILE);
    qkv_kernel<<<gq, 256, SMEM_SZ>>>(p_h1h, p_Wqh, p_Wkh, p_Wvh, bq, bk, bv,
                                     p_qh, p_kh, p_vh);

    colsum_qk_kernel<<<64, 512>>>();
    stage1_kernel<<<(NH * L_SEQ) / 8, 256>>>();
    colsum_w_kernel<<<64, 512>>>();
    stage2_kernel<<<(NH * L_SEQ) / 8, 256>>>();
    softmax_head_kernel<<<NH, 1024>>>();
    kv_kernel<<<dim3(32, NH), 256>>>();
    o_kernel<<<dim3(L_SEQ / 32, NH), 256>>>();

    // O-proj -> g_sa (fp32), K=512
    dim3 go(D_MOD / TILE, L_SEQ / TILE);
    mm_kernel<0,0><<<go, 256, SMEM_SZ>>>(p_oh, p_Woh, bo, nullptr, p_sa, nullptr,
                                         D_MOD, D_MOD, 8);

    addln2_kernel<<<BATCH * L_SEQ, 128>>>(x, g2, be2);

    // FFN1: K=512 -> nIter=8
    dim3 gf1(FF / TILE, (BATCH * L_SEQ) / TILE);
    mm_kernel<2,1><<<gf1, 256, SMEM_SZ>>>(p_ln2h, p_W1h, b1, nullptr, nullptr, p_th,
                                          FF, D_MOD, 8);

    // FFN2: K=2048 -> nIter=32; residual = x + sa (x2 never materialized)
    dim3 gf2(D_MOD / TILE, (BATCH * L_SEQ) / TILE);
    mm_kernel<4,0><<<gf2, 256, SMEM_SZ>>>(p_th, p_W2h, b2, x, out, nullptr,
                                          D_MOD, FF, 32);
}

// round 7
// speedup vs baseline: 3.6405x; 1.0039x over previous
#include <cuda_runtime.h>
#include <cuda_fp16.h>
#include <math.h>
#include <stdint.h>

// ---------------- problem constants ----------------
#define L_SEQ 16384
#define D_MOD 512
#define NH 8
#define DH 64
#define FF 2048
#define BATCH 2
#define EPS_F 1e-6f

// GEMM tiling
#define TILE 128
#define KC 64
#define AROW_B 144                      // 128B data + 16B pad
#define HALF_STAGE (128 * AROW_B)       // 18432
#define STAGE_B (2 * HALF_STAGE)        // 36864
#define SMEM_SZ (3 * STAGE_B)           // 110592

// ---------------- scratch (static device globals; no allocation) ----------------
__device__ __align__(128) __half g_h1h[L_SEQ * D_MOD];            // ln1(x[0]) fp16
__device__ __align__(128) __half g_oh [L_SEQ * D_MOD];            // attn out fp16
__device__ __align__(128) __half g_ln2h[BATCH * L_SEQ * D_MOD];   // ln2 fp16
__device__ __align__(128) __half g_th [(size_t)BATCH * L_SEQ * FF]; // gelu(ffn1) fp16
__device__ __align__(128) __half g_Wqh[D_MOD * D_MOD];            // W^T fp16
__device__ __align__(128) __half g_Wkh[D_MOD * D_MOD];
__device__ __align__(128) __half g_Wvh[D_MOD * D_MOD];
__device__ __align__(128) __half g_Woh[D_MOD * D_MOD];
__device__ __align__(128) __half g_W1h[FF * D_MOD];
__device__ __align__(128) __half g_W2h[D_MOD * FF];

__device__ __align__(128) __half g_qh[L_SEQ * D_MOD];             // q,k,v fp16
__device__ __align__(128) __half g_kh[L_SEQ * D_MOD];
__device__ __align__(128) __half g_vh[L_SEQ * D_MOD];
__device__ __align__(16) float g_sa[L_SEQ * D_MOD];

__device__ float g_ksum[D_MOD], g_qsum[D_MOD];
__device__ float g_kwsum[D_MOD], g_qwsum[D_MOD];
__device__ float g_sink_in[NH * L_SEQ];
__device__ float g_src_out[NH * L_SEQ];
__device__ float g_alloc[NH * L_SEQ];
__device__ float g_cs[NH * L_SEQ];
__device__ float g_hmax[NH], g_hsum[NH];
__device__ float g_kv[NH * DH * DH];

// ---------------- PTX helpers (baseline sm_80+ only) ----------------
__device__ __forceinline__ uint32_t sm_u32(const void* p) {
    uint32_t a;
    asm("{ .reg .u64 t; cvta.to.shared.u64 t, %1; cvt.u32.u64 %0, t; }" : "=r"(a) : "l"(p));
    return a;
}
__device__ __forceinline__ void cp16(uint32_t s, const void* g) {
    asm volatile("cp.async.cg.shared.global [%0], [%1], 16;" :: "r"(s), "l"(g));
}
__device__ __forceinline__ void cp_commit() {
    asm volatile("cp.async.commit_group;" ::: "memory");
}
__device__ __forceinline__ void ldsm4(uint32_t* r, uint32_t addr) {
    asm volatile("ldmatrix.sync.aligned.m8n8.x4.shared.b16 {%0,%1,%2,%3}, [%4];"
                 : "=r"(r[0]), "=r"(r[1]), "=r"(r[2]), "=r"(r[3]) : "r"(addr));
}
__device__ __forceinline__ void mma16816(float* d, const uint32_t* a, const uint32_t* b) {
    asm volatile(
        "mma.sync.aligned.m16n8k16.row.col.f32.f16.f16.f32 "
        "{%0,%1,%2,%3}, {%4,%5,%6,%7}, {%8,%9}, {%0,%1,%2,%3};"
        : "+f"(d[0]), "+f"(d[1]), "+f"(d[2]), "+f"(d[3])
        : "r"(a[0]), "r"(a[1]), "r"(a[2]), "r"(a[3]), "r"(b[0]), "r"(b[1]));
}

// ---------------- fused prep: zero accumulators + all weight transposes ----------------
__global__ void prep_kernel(const float* __restrict__ Wq, const float* __restrict__ Wk,
                            const float* __restrict__ Wv, const float* __restrict__ Wo,
                            const float* __restrict__ W1, const float* __restrict__ W2,
                            __half* __restrict__ Wqh, __half* __restrict__ Wkh,
                            __half* __restrict__ Wvh, __half* __restrict__ Woh,
                            __half* __restrict__ W1h, __half* __restrict__ W2h) {
    int b = blockIdx.x;
    if (b == 3072) {
        int t = threadIdx.y * 32 + threadIdx.x;  // 256
        for (int i = t; i < 4 * D_MOD; i += 256) {
            if (i < D_MOD) g_ksum[i] = 0.f;
            else if (i < 2 * D_MOD) g_qsum[i - D_MOD] = 0.f;
            else if (i < 3 * D_MOD) g_kwsum[i - 2 * D_MOD] = 0.f;
            else g_qwsum[i - 3 * D_MOD] = 0.f;
        }
        for (int i = t; i < NH * DH * DH; i += 256) g_kv[i] = 0.f;
        return;
    }
    const float* W; __half* Wt; int K, N, tix;
    if (b < 1024) {
        K = D_MOD; N = D_MOD;
        int w = b >> 8; tix = b & 255;
        W = (w == 0) ? Wq : (w == 1) ? Wk : (w == 2) ? Wv : Wo;
        Wt = (w == 0) ? Wqh : (w == 1) ? Wkh : (w == 2) ? Wvh : Woh;
    } else if (b < 2048) {
        K = D_MOD; N = FF; tix = b - 1024; W = W1; Wt = W1h;
    } else {
        K = FF; N = D_MOD; tix = b - 2048; W = W2; Wt = W2h;
    }
    int ntx = N / 32;
    int bx = tix % ntx, by = tix / ntx;
    __shared__ float tile[32][33];
    int k0 = by * 32, n0 = bx * 32;
    int tx = threadIdx.x, ty = threadIdx.y;  // 32 x 8
    for (int i = ty; i < 32; i += 8) tile[i][tx] = W[(size_t)(k0 + i) * N + n0 + tx];
    __syncthreads();
    for (int i = ty; i < 32; i += 8)
        Wt[(size_t)(n0 + i) * K + k0 + tx] = __float2half_rn(tile[tx][i]);
}

// ---------------- layernorm on x[0] -> fp16 h1 ----------------
__global__ void ln1_kernel(const float* __restrict__ x,
                           const float* __restrict__ g,
                           const float* __restrict__ be) {
    __shared__ float sh1[4], sh2[4];
    int row = blockIdx.x;
    int t = threadIdx.x;  // 128
    const float* xr = x + (size_t)row * D_MOD;
    float v0 = xr[t], v1 = xr[t + 128], v2 = xr[t + 256], v3 = xr[t + 384];
    float s = v0 + v1 + v2 + v3;
    float s2 = v0 * v0 + v1 * v1 + v2 * v2 + v3 * v3;
    #pragma unroll
    for (int o = 16; o > 0; o >>= 1) {
        s += __shfl_down_sync(0xffffffffu, s, o);
        s2 += __shfl_down_sync(0xffffffffu, s2, o);
    }
    if ((t & 31) == 0) { sh1[t >> 5] = s; sh2[t >> 5] = s2; }
    __syncthreads();
    s = sh1[0] + sh1[1] + sh1[2] + sh1[3];
    s2 = sh2[0] + sh2[1] + sh2[2] + sh2[3];
    float m = s * (1.f / D_MOD);
    float rstd = rsqrtf(s2 * (1.f / D_MOD) - m * m + 1e-5f);
    __half* op = g_h1h + (size_t)row * D_MOD;
    op[t]       = __float2half_rn((v0 - m) * rstd * g[t]       + be[t]);
    op[t + 128] = __float2half_rn((v1 - m) * rstd * g[t + 128] + be[t + 128]);
    op[t + 256] = __float2half_rn((v2 - m) * rstd * g[t + 256] + be[t + 256]);
    op[t + 384] = __float2half_rn((v3 - m) * rstd * g[t + 384] + be[t + 384]);
}

// ---------------- x+sa; ln2 -> fp16 ----------------
__global__ void addln2_kernel(const float* __restrict__ x,
                              const float* __restrict__ g,
                              const float* __restrict__ be) {
    __shared__ float sh1[4], sh2[4];
    int row = blockIdx.x;
    int l = row & (L_SEQ - 1);
    int t = threadIdx.x;  // 128
    const float* xr = x + (size_t)row * D_MOD;
    const float* sr = g_sa + (size_t)l * D_MOD;
    float v0 = xr[t] + sr[t];
    float v1 = xr[t + 128] + sr[t + 128];
    float v2 = xr[t + 256] + sr[t + 256];
    float v3 = xr[t + 384] + sr[t + 384];
    float s = v0 + v1 + v2 + v3;
    float s2 = v0 * v0 + v1 * v1 + v2 * v2 + v3 * v3;
    #pragma unroll
    for (int o = 16; o > 0; o >>= 1) {
        s += __shfl_down_sync(0xffffffffu, s, o);
        s2 += __shfl_down_sync(0xffffffffu, s2, o);
    }
    if ((t & 31) == 0) { sh1[t >> 5] = s; sh2[t >> 5] = s2; }
    __syncthreads();
    s = sh1[0] + sh1[1] + sh1[2] + sh1[3];
    s2 = sh2[0] + sh2[1] + sh2[2] + sh2[3];
    float m = s * (1.f / D_MOD);
    float rstd = rsqrtf(s2 * (1.f / D_MOD) - m * m + 1e-5f);
    __half* op = g_ln2h + (size_t)row * D_MOD;
    op[t]       = __float2half_rn((v0 - m) * rstd * g[t]       + be[t]);
    op[t + 128] = __float2half_rn((v1 - m) * rstd * g[t + 128] + be[t + 128]);
    op[t + 256] = __float2half_rn((v2 - m) * rstd * g[t + 256] + be[t + 256]);
    op[t + 384] = __float2half_rn((v3 - m) * rstd * g[t + 384] + be[t + 384]);
}

// ---------------- column sums of q, k (wide grid: 512 blocks x 32 rows) ----------------
__global__ void colsum_qk_kernel() {
    int c = threadIdx.x;                 // 512
    int r0 = blockIdx.x * 32;            // 512 blocks
    float sq = 0.f, sk = 0.f;
    #pragma unroll 4
    for (int r = r0; r < r0 + 32; r++) {
        sq += __half2float(g_qh[(size_t)r * D_MOD + c]);
        sk += __half2float(g_kh[(size_t)r * D_MOD + c]);
    }
    atomicAdd(&g_qsum[c], sq);
    atomicAdd(&g_ksum[c], sk);
}

// ---------------- stage1 + fused weighted colsum ----------------
// Each block = 8 consecutive rows of ONE head (blocks/head = 2048).
__global__ void stage1_kernel() {
    __shared__ float swq[64], swk[64];
    int t = threadIdx.x;  // 256
    if (t < 64) { swq[t] = 0.f; swk[t] = 0.f; }
    __syncthreads();
    int w = blockIdx.x * 8 + (t >> 5);
    int lane = t & 31;
    int h = w >> 14;
    int l = w & (L_SEQ - 1);
    const __half* qr = g_qh + (size_t)l * D_MOD + h * DH;
    const __half* kr = g_kh + (size_t)l * D_MOD + h * DH;
    const float* ks = g_ksum + h * DH;
    const float* qs = g_qsum + h * DH;
    float q0 = __half2float(qr[lane]), q1 = __half2float(qr[lane + 32]);
    float k0 = __half2float(kr[lane]), k1 = __half2float(kr[lane + 32]);
    float a = (q0 + EPS_F) * (ks[lane] + EPS_F) + (q1 + EPS_F) * (ks[lane + 32] + EPS_F);
    float b = (k0 + EPS_F) * (qs[lane] + EPS_F) + (k1 + EPS_F) * (qs[lane + 32] + EPS_F);
    #pragma unroll
    for (int o = 16; o > 0; o >>= 1) {
        a += __shfl_xor_sync(0xffffffffu, a, o);
        b += __shfl_xor_sync(0xffffffffu, b, o);
    }
    float si = 1.f / a;
    float so = 1.f / b;
    if (lane == 0) {
        g_sink_in[h * L_SEQ + l] = si;
        g_src_out[h * L_SEQ + l] = so;
    }
    atomicAdd(&swq[lane], q0 * si);
    atomicAdd(&swq[lane + 32], q1 * si);
    atomicAdd(&swk[lane], k0 * so);
    atomicAdd(&swk[lane + 32], k1 * so);
    __syncthreads();
    if (t < 64) {
        int bh = blockIdx.x >> 11;  // head of this block
        atomicAdd(&g_qwsum[bh * DH + t], swq[t]);
        atomicAdd(&g_kwsum[bh * DH + t], swk[t]);
    }
}

__global__ void stage2_kernel() {
    int w = (blockIdx.x * blockDim.x + threadIdx.x) >> 5;
    int lane = threadIdx.x & 31;
    int h = w >> 14;
    int l = w & (L_SEQ - 1);
    const __half* qr = g_qh + (size_t)l * D_MOD + h * DH;
    const __half* kr = g_kh + (size_t)l * D_MOD + h * DH;
    const float* kw = g_kwsum + h * DH;
    const float* qw = g_qwsum + h * DH;
    float a = (__half2float(qr[lane]) + EPS_F) * (kw[lane] + EPS_F)
            + (__half2float(qr[lane + 32]) + EPS_F) * (kw[lane + 32] + EPS_F);
    float b = (__half2float(kr[lane]) + EPS_F) * (qw[lane] + EPS_F)
            + (__half2float(kr[lane + 32]) + EPS_F) * (qw[lane + 32] + EPS_F);
    #pragma unroll
    for (int o = 16; o > 0; o >>= 1) {
        a += __shfl_down_sync(0xffffffffu, a, o);
        b += __shfl_down_sync(0xffffffffu, b, o);
    }
    if (lane == 0) {
        g_alloc[h * L_SEQ + l] = 1.f / (1.f + expf(-a));
        g_cs[h * L_SEQ + l] = fminf(fmaxf(b, -1.f), 1.f);
    }
}

__global__ void softmax_head_kernel() {
    __shared__ float sh[32];
    int h = blockIdx.x;
    int t = threadIdx.x;  // 1024
    const float* cs = g_cs + h * L_SEQ;
    float mx = -1e30f;
    for (int i = t; i < L_SEQ; i += 1024) mx = fmaxf(mx, cs[i]);
    #pragma unroll
    for (int o = 16; o > 0; o >>= 1) mx = fmaxf(mx, __shfl_xor_sync(0xffffffffu, mx, o));
    if ((t & 31) == 0) sh[t >> 5] = mx;
    __syncthreads();
    float bm = sh[0];
    #pragma unroll
    for (int i = 1; i < 32; i++) bm = fmaxf(bm, sh[i]);
    __syncthreads();
    float se = 0.f;
    for (int i = t; i < L_SEQ; i += 1024) se += expf(cs[i] - bm);
    #pragma unroll
    for (int o = 16; o > 0; o >>= 1) se += __shfl_xor_sync(0xffffffffu, se, o);
    if ((t & 31) == 0) sh[t >> 5] = se;
    __syncthreads();
    if (t == 0) {
        float s = 0.f;
        #pragma unroll
        for (int i = 0; i < 32; i++) s += sh[i];
        g_hmax[h] = bm;
        g_hsum[h] = s;
    }
}

__global__ void kv_kernel() {
    __shared__ float sk[8][64];
    __shared__ float sv[8][64];
    int h = blockIdx.y;
    int chunk = blockIdx.x;
    int t = threadIdx.x;
    int drow = t >> 2;
    int mbase = (t & 3) << 4;
    float hmax = g_hmax[h];
    float hscale = (float)L_SEQ / g_hsum[h];
    int l0 = chunk * 512;
    float acc[16];
    #pragma unroll
    for (int j = 0; j < 16; j++) acc[j] = 0.f;
    for (int it = 0; it < 64; it++) {
        int lb = l0 + it * 8;
        #pragma unroll
        for (int j = 0; j < 4; j++) {
            int e = t + j * 256;
            if (e < 512) {
                int r = e >> 6, dd = e & 63;
                sk[r][dd] = __half2float(g_kh[(size_t)(lb + r) * D_MOD + h * DH + dd]);
            } else {
                int e2 = e - 512;
                int r = e2 >> 6, dd = e2 & 63;
                int l = lb + r;
                float comp = expf(g_cs[h * L_SEQ + l] - hmax) * hscale;
                sv[r][dd] = __half2float(g_vh[(size_t)l * D_MOD + h * DH + dd]) * comp;
            }
        }
        __syncthreads();
        #pragma unroll
        for (int r = 0; r < 8; r++) {
            float kd = sk[r][drow];
            #pragma unroll
            for (int j = 0; j < 16; j++) acc[j] += kd * sv[r][mbase + j];
        }
        __syncthreads();
    }
    float* kvp = g_kv + h * DH * DH + drow * DH + mbase;
    #pragma unroll
    for (int j = 0; j < 16; j++) atomicAdd(&kvp[j], acc[j]);
}

// ---------------- o = (q*sink_in) @ kv * alloc -> fp16 ----------------
__global__ void o_kernel() {
    __shared__ float kvs[DH * DH];
    __shared__ float qs[32][64];
    int h = blockIdx.y;
    int chunk = blockIdx.x;
    int t = threadIdx.x;
    for (int e = t; e < DH * DH; e += 256) kvs[e] = g_kv[h * DH * DH + e];
    for (int e = t; e < 32 * 64; e += 256) {
        int r = e >> 6, dd = e & 63;
        int l = chunk * 32 + r;
        qs[r][dd] = __half2float(g_qh[(size_t)l * D_MOD + h * DH + dd]) * g_sink_in[h * L_SEQ + l];
    }
    __syncthreads();
    int r = t >> 3;
    int cg = (t & 7) * 8;
    float acc[8];
    #pragma unroll
    for (int j = 0; j < 8; j++) acc[j] = 0.f;
    #pragma unroll
    for (int dd = 0; dd < 64; dd++) {
        float qv = qs[r][dd];
        #pragma unroll
        for (int j = 0; j < 8; j++) acc[j] += qv * kvs[dd * 64 + cg + j];
    }
    int l = chunk * 32 + r;
    float al = g_alloc[h * L_SEQ + l];
    __half* op = g_oh + (size_t)l * D_MOD + h * DH + cg;
    #pragma unroll
    for (int j = 0; j < 8; j++) op[j] = __float2half_rn(acc[j] * al);
}

// =====================================================================
// GEMM machinery (frozen mainloop: KC=64, 3 stages, 1 sync/iter)
// =====================================================================
__device__ __forceinline__ void mm_mainloop(
    uint32_t sb, const __half* A, const __half* B, int K, int nIter,
    int rowA0, int colB0, int tid, int wid, int lane, int wm, int wn,
    float (*acc)[4][4]) {
    const int lrow = tid >> 1;
    const int lcolB = (tid & 1) * 64;

    auto load_stage = [&](int slot, int it) {
        const __half* Ag = A + (size_t)(rowA0 + lrow) * K + it * KC + (lcolB >> 1);
        const __half* Bg = B + (size_t)(colB0 + lrow) * K + it * KC + (lcolB >> 1);
        uint32_t sA = sb + slot * STAGE_B + lrow * AROW_B + lcolB;
        uint32_t sB = sA + HALF_STAGE;
        cp16(sA, Ag);       cp16(sA + 16, Ag + 8);
        cp16(sA + 32, Ag + 16); cp16(sA + 48, Ag + 24);
        cp16(sB, Bg);       cp16(sB + 16, Bg + 8);
        cp16(sB + 32, Bg + 16); cp16(sB + 48, Bg + 24);
        cp_commit();
    };

    auto compute_stage = [&](int slot) {
        uint32_t aB = sb + slot * STAGE_B;
        uint32_t bB = aB + HALF_STAGE;
        #pragma unroll
        for (int ks = 0; ks < 4; ks++) {
            uint32_t af[4][4], bfr[2][4];
            #pragma unroll
            for (int mf = 0; mf < 4; mf++)
                ldsm4(af[mf], aB + (uint32_t)((wm + mf * 16 + (lane & 15)) * AROW_B
                                              + ks * 32 + ((lane >> 4) << 4)));
            #pragma unroll
            for (int g = 0; g < 2; g++)
                ldsm4(bfr[g], bB + (uint32_t)((wn + g * 16 + (lane & 7) + ((lane & 16) >> 1)) * AROW_B
                                              + ks * 32 + ((lane & 8) << 1)));
            #pragma unroll
            for (int mf = 0; mf < 4; mf++)
                #pragma unroll
                for (int nf = 0; nf < 4; nf++)
                    mma16816(acc[mf][nf], af[mf], &bfr[nf >> 1][(nf & 1) * 2]);
        }
    };

    load_stage(0, 0);
    load_stage(1, 1);

    int slot = 0, nslot = 2;
    for (int it = 0; it < nIter; it++) {
        asm volatile("cp.async.wait_group 1;" ::: "memory");
        __syncthreads();
        if (it + 2 < nIter) load_stage(nslot, it + 2); else cp_commit();
        compute_stage(slot);
        slot = (slot == 2) ? 0 : slot + 1;
        nslot = (nslot == 2) ? 0 : nslot + 1;
    }
}

// ---------------- fused QKV GEMM ----------------
__global__ void __launch_bounds__(256, 2) qkv_kernel(
    const __half* __restrict__ A,
    const __half* __restrict__ Bq, const __half* __restrict__ Bk, const __half* __restrict__ Bv,
    const float* __restrict__ bq, const float* __restrict__ bk, const float* __restrict__ bv,
    __half* __restrict__ Oq, __half* __restrict__ Ok, __half* __restrict__ Ov) {
    extern __shared__ __align__(128) char smem[];
    uint32_t sb = sm_u32(smem);
    const int tid = threadIdx.x;
    const int wid = tid >> 5, lane = tid & 31;
    const int which = blockIdx.x >> 2;
    const int rowA0 = blockIdx.y * TILE, colB0 = (blockIdx.x & 3) * TILE;
    const int wm = (wid >> 2) * 64, wn = (wid & 3) * 32;

    const __half* B = (which == 0) ? Bq : (which == 1) ? Bk : Bv;
    const float* bias = (which == 0) ? bq : (which == 1) ? bk : bv;
    __half* Ch = (which == 0) ? Oq : (which == 1) ? Ok : Ov;
    const bool sig = (which < 2);

    float acc[4][4][4];
    #pragma unroll
    for (int i = 0; i < 4; i++)
        #pragma unroll
        for (int j = 0; j < 4; j++)
            #pragma unroll
            for (int e = 0; e < 4; e++) acc[i][j][e] = 0.f;

    mm_mainloop(sb, A, B, D_MOD, D_MOD / KC, rowA0, colB0, tid, wid, lane, wm, wn, acc);

    const int lm = lane >> 2;
    const int ln = (lane & 3) * 2;
    #pragma unroll
    for (int mf = 0; mf < 4; mf++) {
        #pragma unroll
        for (int nf = 0; nf < 4; nf++) {
            int m0 = rowA0 + wm + mf * 16 + lm;
            int n0 = colB0 + wn + nf * 8 + ln;
            float b0 = __ldg(&bias[n0]), b1 = __ldg(&bias[n0 + 1]);
            float f0 = acc[mf][nf][0] + b0;
            float f1 = acc[mf][nf][1] + b1;
            float f2 = acc[mf][nf][2] + b0;
            float f3 = acc[mf][nf][3] + b1;
            if (sig) {
                f0 = 1.f / (1.f + expf(-f0)); f1 = 1.f / (1.f + expf(-f1));
                f2 = 1.f / (1.f + expf(-f2)); f3 = 1.f / (1.f + expf(-f3));
            }
            __half2 h0; h0.x = __float2half_rn(f0); h0.y = __float2half_rn(f1);
            __half2 h1; h1.x = __float2half_rn(f2); h1.y = __float2half_rn(f3);
            *(__half2*)(Ch + (size_t)m0 * D_MOD + n0) = h0;
            *(__half2*)(Ch + (size_t)(m0 + 8) * D_MOD + n0) = h1;
        }
    }
}

// ---------------- generic GEMM ----------------
// MODE 0: +bias | 2: gelu | 4: +bias + x[row] + sa[row&mask]
template <int MODE, int OUTH>
__global__ void __launch_bounds__(256, 2) mm_kernel(
    const __half* __restrict__ A, const __half* __restrict__ B,
    const float* __restrict__ bias, const float* __restrict__ resx,
    float* __restrict__ Cf, __half* __restrict__ Ch,
    int N, int K, int nIter) {
    extern __shared__ __align__(128) char smem[];
    uint32_t sb = sm_u32(smem);
    const int tid = threadIdx.x;
    const int wid = tid >> 5, lane = tid & 31;
    const int rowA0 = blockIdx.y * TILE, colB0 = blockIdx.x * TILE;
    const int wm = (wid >> 2) * 64, wn = (wid & 3) * 32;

    float acc[4][4][4];
    #pragma unroll
    for (int i = 0; i < 4; i++)
        #pragma unroll
        for (int j = 0; j < 4; j++)
            #pragma unroll
            for (int e = 0; e < 4; e++) acc[i][j][e] = 0.f;

    mm_mainloop(sb, A, B, K, nIter, rowA0, colB0, tid, wid, lane, wm, wn, acc);

    const int lm = lane >> 2;
    const int ln = (lane & 3) * 2;
    #pragma unroll
    for (int mf = 0; mf < 4; mf++) {
        #pragma unroll
        for (int nf = 0; nf < 4; nf++) {
            int m0 = rowA0 + wm + mf * 16 + lm;
            int n0 = colB0 + wn + nf * 8 + ln;
            float b0 = __ldg(&bias[n0]), b1 = __ldg(&bias[n0 + 1]);
            float f0 = acc[mf][nf][0] + b0;
            float f1 = acc[mf][nf][1] + b1;
            float f2 = acc[mf][nf][2] + b0;
            float f3 = acc[mf][nf][3] + b1;
            if (MODE == 2) {
                f0 = 0.5f * f0 * (1.f + erff(f0 * 0.70710678118654752f));
                f1 = 0.5f * f1 * (1.f + erff(f1 * 0.70710678118654752f));
                f2 = 0.5f * f2 * (1.f + erff(f2 * 0.70710678118654752f));
                f3 = 0.5f * f3 * (1.f + erff(f3 * 0.70710678118654752f));
            } else if (MODE == 4) {
                int l0r = m0 & (L_SEQ - 1), l1r = (m0 + 8) & (L_SEQ - 1);
                float2 r0 = *(const float2*)(resx + (size_t)m0 * N + n0);
                float2 r1 = *(const float2*)(resx + (size_t)(m0 + 8) * N + n0);
                float2 s0 = *(const float2*)(g_sa + (size_t)l0r * N + n0);
                float2 s1 = *(const float2*)(g_sa + (size_t)l1r * N + n0);
                f0 += r0.x + s0.x; f1 += r0.y + s0.y;
                f2 += r1.x + s1.x; f3 += r1.y + s1.y;
            }
            if (OUTH) {
                __half2 h0; h0.x = __float2half_rn(f0); h0.y = __float2half_rn(f1);
                __half2 h1; h1.x = __float2half_rn(f2); h1.y = __float2half_rn(f3);
                *(__half2*)(Ch + (size_t)m0 * N + n0) = h0;
                *(__half2*)(Ch + (size_t)(m0 + 8) * N + n0) = h1;
            } else {
                float2 v0; v0.x = f0; v0.y = f1;
                float2 v1; v1.x = f2; v1.y = f3;
                *(float2*)(Cf + (size_t)m0 * N + n0) = v0;
                *(float2*)(Cf + (size_t)(m0 + 8) * N + n0) = v1;
            }
        }
    }
}

// ---------------- launcher ----------------
extern "C" void kernel_launch(void* const* d_in, const int* in_sizes, int n_in,
                              void* d_out, int out_size) {
    (void)in_sizes; (void)n_in; (void)out_size;
    const float* x   = (const float*)d_in[0];
    const float* Wq  = (const float*)d_in[1];
    const float* bq  = (const float*)d_in[2];
    const float* Wk  = (const float*)d_in[3];
    const float* bk  = (const float*)d_in[4];
    const float* Wv  = (const float*)d_in[5];
    const float* bv  = (const float*)d_in[6];
    const float* Wo  = (const float*)d_in[7];
    const float* bo  = (const float*)d_in[8];
    const float* W1  = (const float*)d_in[9];
    const float* b1  = (const float*)d_in[10];
    const float* W2  = (const float*)d_in[11];
    const float* b2  = (const float*)d_in[12];
    const float* g1  = (const float*)d_in[13];
    const float* be1 = (const float*)d_in[14];
    const float* g2  = (const float*)d_in[15];
    const float* be2 = (const float*)d_in[16];
    float* out = (float*)d_out;

    __half *p_h1h, *p_oh, *p_ln2h, *p_th, *p_Wqh, *p_Wkh, *p_Wvh, *p_Woh, *p_W1h, *p_W2h;
    __half *p_qh, *p_kh, *p_vh;
    float *p_sa;
    cudaGetSymbolAddress((void**)&p_h1h, g_h1h);
    cudaGetSymbolAddress((void**)&p_oh, g_oh);
    cudaGetSymbolAddress((void**)&p_ln2h, g_ln2h);
    cudaGetSymbolAddress((void**)&p_th, g_th);
    cudaGetSymbolAddress((void**)&p_Wqh, g_Wqh);
    cudaGetSymbolAddress((void**)&p_Wkh, g_Wkh);
    cudaGetSymbolAddress((void**)&p_Wvh, g_Wvh);
    cudaGetSymbolAddress((void**)&p_Woh, g_Woh);
    cudaGetSymbolAddress((void**)&p_W1h, g_W1h);
    cudaGetSymbolAddress((void**)&p_W2h, g_W2h);
    cudaGetSymbolAddress((void**)&p_qh, g_qh);
    cudaGetSymbolAddress((void**)&p_kh, g_kh);
    cudaGetSymbolAddress((void**)&p_vh, g_vh);
    cudaGetSymbolAddress((void**)&p_sa, g_sa);

    cudaFuncSetAttribute(qkv_kernel, cudaFuncAttributeMaxDynamicSharedMemorySize, SMEM_SZ);
    cudaFuncSetAttribute(mm_kernel<0,0>, cudaFuncAttributeMaxDynamicSharedMemorySize, SMEM_SZ);
    cudaFuncSetAttribute(mm_kernel<2,1>, cudaFuncAttributeMaxDynamicSharedMemorySize, SMEM_SZ);
    cudaFuncSetAttribute(mm_kernel<4,0>, cudaFuncAttributeMaxDynamicSharedMemorySize, SMEM_SZ);

    dim3 wblk(32, 8);
    prep_kernel<<<3073, wblk>>>(Wq, Wk, Wv, Wo, W1, W2,
                                p_Wqh, p_Wkh, p_Wvh, p_Woh, p_W1h, p_W2h);
    ln1_kernel<<<L_SEQ, 128>>>(x, g1, be1);

    // fused QKV: grid (12, 128), K=512 -> nIter=8
    dim3 gq(12, L_SEQ / TILE);
    qkv_kernel<<<gq, 256, SMEM_SZ>>>(p_h1h, p_Wqh, p_Wkh, p_Wvh, bq, bk, bv,
                                     p_qh, p_kh, p_vh);

    colsum_qk_kernel<<<512, 512>>>();
    stage1_kernel<<<(NH * L_SEQ) / 8, 256>>>();   // includes weighted colsums
    stage2_kernel<<<(NH * L_SEQ) / 8, 256>>>();
    softmax_head_kernel<<<NH, 1024>>>();
    kv_kernel<<<dim3(32, NH), 256>>>();
    o_kernel<<<dim3(L_SEQ / 32, NH), 256>>>();

    // O-proj -> g_sa (fp32), K=512
    dim3 go(D_MOD / TILE, L_SEQ / TILE);
    mm_kernel<0,0><<<go, 256, SMEM_SZ>>>(p_oh, p_Woh, bo, nullptr, p_sa, nullptr,
                                         D_MOD, D_MOD, 8);

    addln2_kernel<<<BATCH * L_SEQ, 128>>>(x, g2, be2);

    // FFN1: K=512 -> nIter=8
    dim3 gf1(FF / TILE, (BATCH * L_SEQ) / TILE);
    mm_kernel<2,1><<<gf1, 256, SMEM_SZ>>>(p_ln2h, p_W1h, b1, nullptr, nullptr, p_th,
                                          FF, D_MOD, 8);

    // FFN2: K=2048 -> nIter=32; residual = x + sa
    dim3 gf2(D_MOD / TILE, (BATCH * L_SEQ) / TILE);
    mm_kernel<4,0><<<gf2, 256, SMEM_SZ>>>(p_th, p_W2h, b2, x, out, nullptr,
                                          D_MOD, FF, 32);
}